// round 5
// baseline (speedup 1.0000x reference)
#include <cuda_runtime.h>
#include <cuda_bf16.h>

// Libdevice DOUBLE transcendentals (<1 ulp), rounded to float. This bit-matches
// glibc/aarch64 (ARM optimized-routines) float sinf/cosf/logf/expf, which are
// computed internally in double precision — the implementation the XLA:CPU
// reference lowers to.
extern "C" {
__device__ double __nv_sin(double);
__device__ double __nv_cos(double);
__device__ double __nv_log(double);
__device__ double __nv_exp(double);
}

__device__ __forceinline__ float sinf_cr(float x) { return (float)__nv_sin((double)x); }
__device__ __forceinline__ float cosf_cr(float x) { return (float)__nv_cos((double)x); }
__device__ __forceinline__ float logf_cr(float x) { return (float)__nv_log((double)x); }
__device__ __forceinline__ float expf_cr(float x) { return (float)__nv_exp((double)x); }

// Problem constants (B, H, W, SCALE) = (8, 384, 1280, 2)
#define BD   8
#define HD   384
#define WD   1280
#define LHD  (HD / 4)    // 96
#define LWD  (WD / 4)    // 320
#define NCELL (BD * LHD * LWD)  // 245760

// Reference (XLA:CPU, LLVM default = NO fma contraction):
//   e  = fsub(fmul(a3, c), fmul(a1, b3)),  b3 = -cos
//   lg = fsub(log(max(|e1|, pm)), log(max(|e2|, pm))), clipped to [-10, 10]
__device__ __forceinline__ float log_ratio(float s3, float n3,
                                           float m1, float c1, float c2)
{
    const float pm = 1e-6f;
    const float t  = __fmul_rn(m1, n3);             // fl(a1 * (-cos)), shared
    float e1 = __fsub_rn(__fmul_rn(s3, c1), t);
    float e2 = __fsub_rn(__fmul_rn(s3, c2), t);
    float la = logf_cr(fmaxf(fabsf(e1), pm));
    float lb = logf_cr(fmaxf(fabsf(e2), pm));
    float v  = __fsub_rn(la, lb);
    return fminf(fmaxf(v, -10.0f), 10.0f);
}

__global__ __launch_bounds__(256)
void sno_kernel(const float* __restrict__ depth,
                const float* __restrict__ ang,
                const float* __restrict__ intr,
                float* __restrict__ out)
{
    int tid = blockIdx.x * blockDim.x + threadIdx.x;
    if (tid >= NCELL) return;

    int cx = tid % LWD;
    int t  = tid / LWD;
    int cy = t % LHD;
    int b  = t / LHD;

    const float fx = intr[b * 9 + 0];
    const float bx = intr[b * 9 + 2];
    const float fy = intr[b * 9 + 4];
    const float by = intr[b * 9 + 5];

    const int y0 = cy * 4;   // block top row    (== yy0 - 2)
    const int x0 = cx * 4;   // block left col   (== xx0 - 2)

    const float* __restrict__ angh = ang + (size_t)(b * 2 + 0) * HD * WD;
    const float* __restrict__ angv = ang + (size_t)(b * 2 + 1) * HD * WD;

    // logh needed at column offsets {-2,-1,0} (local col 0..2), all 4 rows
    // logv needed at row offsets {-2,-1,0} (local row 0..2), all 4 cols
    float lh[4][3];
    float lv[3][4];

    #pragma unroll
    for (int r = 0; r < 4; ++r) {
        const int y = y0 + r;
        const float yf = (float)y;
        // ty = (yy - by)/fy ; a1 = ty*ty + 1 (non-contracted) ; v1 = -ty
        const float ty  = __fdiv_rn(__fsub_rn(yf, by), fy);
        const float a1  = __fadd_rn(__fmul_rn(ty, ty), 1.0f);
        const float v1  = -ty;
        const float v2  = -__fdiv_rn(__fsub_rn(__fadd_rn(yf, 1.0f), by), fy);
        #pragma unroll
        for (int c = 0; c < 4; ++c) {
            const int x = x0 + c;
            const float xf = (float)x;
            const float tx = __fdiv_rn(__fsub_rn(xf, bx), fx);
            if (c < 3) {
                const float b1 = -tx;
                const float b2 = -__fdiv_rn(__fsub_rn(__fadd_rn(xf, 1.0f), bx), fx);
                const float ah = angh[(size_t)y * WD + x];
                const float s  = sinf_cr(ah);
                const float n3 = -cosf_cr(ah);
                lh[r][c] = log_ratio(s, n3, a1, b1, b2);
            }
            if (r < 3) {
                const float u1 = __fadd_rn(__fmul_rn(tx, tx), 1.0f);
                const float av = angv[(size_t)y * WD + x];
                const float s  = sinf_cr(av);
                const float n3 = -cosf_cr(av);
                lv[r][c] = log_ratio(s, n3, u1, v1, v2);
            }
        }
    }

    // d[row][col]: row = mm+2, col = nn+2  -> pixel (y0+row, x0+col)
    float d[4][4];
    d[2][2] = logf_cr(depth[tid]);   // depth layout (B,1,LH,LW) -> linear == tid

    // 15 paths, fully unrolled; all index logic folds at compile time.
    #pragma unroll
    for (int m = 0; m < 4; ++m) {
        #pragma unroll
        for (int n = 0; n < 4; ++n) {
            if (m == 0 && n == 0) continue;
            const int mm = (m & 1) ? -((m + 1) >> 1) : (m >> 1);
            const int nn = (n & 1) ? -((n + 1) >> 1) : (n >> 1);

            int lx1 = 0, ly1 = 0, ch1 = 0, dx1 = 0, dy1 = 0;
            int lx2 = 0, ly2 = 0, ch2 = 0, dx2 = 0, dy2 = 0;
            float s1 = 0.0f, s2 = 0.0f;
            const bool has1 = (nn != 0);
            const bool has2 = (mm != 0);
            if (nn < 0)      { lx1 = nn;     ly1 = mm; ch1 = 0; dx1 = nn + 1; dy1 = mm;     s1 = -1.0f; }
            else if (nn > 0) { lx1 = nn - 1; ly1 = mm; ch1 = 0; dx1 = nn - 1; dy1 = mm;     s1 =  1.0f; }
            if (mm > 0)      { lx2 = nn; ly2 = mm - 1; ch2 = 1; dx2 = nn;     dy2 = mm - 1; s2 =  1.0f; }
            else if (mm < 0) { lx2 = nn; ly2 = mm;     ch2 = 1; dx2 = nn;     dy2 = mm + 1; s2 = -1.0f; }
            if (!has1) { lx1 = lx2; ly1 = ly2; ch1 = ch2; dx1 = dx2; dy1 = dy2; s1 = s2; }
            if (!has2) { lx2 = lx1; ly2 = ly1; ch2 = ch1; dx2 = dx1; dy2 = dy1; s2 = s1; }

            const float l1 = (ch1 == 0) ? lh[ly1 + 2][lx1 + 2] : lv[ly1 + 2][lx1 + 2];
            const float l2 = (ch2 == 0) ? lh[ly2 + 2][lx2 + 2] : lv[ly2 + 2][lx2 + 2];

            // ref order: ((d1 + s1*l1) + d2 + s2*l2) * 0.5; s in {±1} exact.
            float acc = __fadd_rn(d[dy1 + 2][dx1 + 2], __fmul_rn(s1, l1));
            acc = __fadd_rn(acc, d[dy2 + 2][dx2 + 2]);
            acc = __fadd_rn(acc, __fmul_rn(s2, l2));
            d[mm + 2][nn + 2] = __fmul_rn(acc, 0.5f);
        }
    }

    // exp + vectorized store (x0 is 16B-aligned: multiple of 4 floats)
    #pragma unroll
    for (int r = 0; r < 4; ++r) {
        const int y = y0 + r;
        float4 o;
        o.x = expf_cr(d[r][0]);
        o.y = expf_cr(d[r][1]);
        o.z = expf_cr(d[r][2]);
        o.w = expf_cr(d[r][3]);
        *reinterpret_cast<float4*>(&out[((size_t)b * HD + y) * WD + x0]) = o;
    }
}

extern "C" void kernel_launch(void* const* d_in, const int* in_sizes, int n_in,
                              void* d_out, int out_size)
{
    const float* depth = (const float*)d_in[0];
    const float* ang   = (const float*)d_in[1];
    const float* intr  = (const float*)d_in[2];
    float* out = (float*)d_out;

    const int threads = 256;
    const int blocks = (NCELL + threads - 1) / threads;
    sno_kernel<<<blocks, threads>>>(depth, ang, intr, out);
}

// round 6
// speedup vs baseline: 2.2070x; 2.2070x over previous
#include <cuda_runtime.h>
#include <cuda_bf16.h>

// Libdevice doubles used ONLY for one-shot per-block table init.
extern "C" {
__device__ double __nv_log(double);
__device__ double __nv_exp(double);
}

// Problem constants (B, H, W, SCALE) = (8, 384, 1280, 2)
#define BD   8
#define HD   384
#define WD   1280
#define LHD  (HD / 4)    // 96
#define LWD  (WD / 4)    // 320
#define NCELL (BD * LHD * LWD)  // 245760

// ---- constants ----
#define BIGMAGIC  6755399441055744.0          // 2^52 + 2^51
#define INVPIO2   6.36619772367581382433e-01
#define PIO2_1    1.57079632673412561417e+00  // 33-bit head of pi/2
#define PIO2_1T   6.07710050650619224932e-11  // tail
#define LN2HI     6.93147180369123816490e-01
#define LN2LO     1.90821492927058770002e-10
#define INVLN2_32 46.166241308446828384
#define LN2_32HI  (6.93147180369123816490e-01 / 32.0)
#define LN2_32LO  (1.90821492927058770002e-10 / 32.0)

// Fused sin/cos: double-internal, |x| small (ang ~ N(0,1)), error ~2^-50.
// Float-rounded results bit-match libdevice __nv_sin/__nv_cos casts (verified
// accuracy class), which bit-match the aarch64 glibc reference.
__device__ __forceinline__ void dsincosf(float xf, float* sf, float* cf)
{
    double x = (double)xf;
    double t = __fma_rn(x, INVPIO2, BIGMAGIC);
    int    k = __double2loint(t);
    double fk = t - BIGMAGIC;
    double r = __fma_rn(fk, -PIO2_1,  x);
    r        = __fma_rn(fk, -PIO2_1T, r);
    double z = r * r;
    // FDLIBM sin poly (degree 13)
    double sp = __fma_rn(1.58969099521155010221e-10, z, -2.50507602534068634195e-08);
    sp = __fma_rn(sp, z,  2.75573137070700676789e-06);
    sp = __fma_rn(sp, z, -1.98412698298579493134e-04);
    sp = __fma_rn(sp, z,  8.33333333332248946124e-03);
    sp = __fma_rn(sp, z, -1.66666666666666324348e-01);
    double s = __fma_rn(sp * z, r, r);
    // FDLIBM cos poly (degree 12), direct Horner with leading 1
    double cp = __fma_rn(-1.13596475577881948265e-11, z, 2.08757232129817482790e-09);
    cp = __fma_rn(cp, z, -2.75573143513906633035e-07);
    cp = __fma_rn(cp, z,  2.48015872894767294178e-05);
    cp = __fma_rn(cp, z, -1.38888888888741095749e-03);
    cp = __fma_rn(cp, z,  4.16666666666666019037e-02);
    cp = __fma_rn(cp, z, -0.5);
    double c = __fma_rn(cp, z, 1.0);
    // quadrant selection (branch-free: SELP + sign flip)
    double s0 = (k & 1) ? c : s;
    double c0 = (k & 1) ? s : c;
    if (k & 2)       s0 = -s0;
    if ((k + 1) & 2) c0 = -c0;
    *sf = (float)s0;
    *cf = (float)c0;
}

__global__ __launch_bounds__(128)
void sno_kernel(const float* __restrict__ depth,
                const float* __restrict__ ang,
                const float* __restrict__ intr,
                float* __restrict__ out)
{
    // ---- per-block transcendental tables ----
    __shared__ double2 s_logtab[128];   // .x = c ~ 1/m_j, .y = -log(c)
    __shared__ double  s_exptab[32];    // 2^(j/32)
    {
        int j = threadIdx.x;
        if (j < 128) {
            double m = 1.0 + ((double)j + 0.5) * 0.0078125;
            double c = 1.0 / m;
            double2 v; v.x = c; v.y = -__nv_log(c);
            s_logtab[j] = v;
            if (j < 32)
                s_exptab[j] = __nv_exp((double)j * (0.69314718055994530942 / 32.0));
        }
    }
    __syncthreads();

    // table-based double log of a positive float; abs error ~2^-42
    auto dlogf = [&](float xf) -> float {
        double x = (double)xf;
        long long i = __double_as_longlong(x);
        int e = (int)(i >> 52) - 1023;
        int j = (int)(i >> 45) & 127;
        double m = __longlong_as_double((i & 0xFFFFFFFFFFFFFULL) | 0x3FF0000000000000ULL);
        double2 cl = s_logtab[j];
        double r  = __fma_rn(m, cl.x, -1.0);
        double r2 = r * r;
        double w  = __fma_rn(-0.25, r, 1.0 / 3.0);
        w         = __fma_rn(w, r, -0.5);
        double p  = __fma_rn(r2, w, r);            // log1p(r)
        double de = (double)e;
        double res = cl.y + p;
        res = __fma_rn(de, LN2LO, res);
        res = __fma_rn(de, LN2HI, res);
        return (float)res;
    };

    // table-based double exp of a float; rel error ~2^-39
    auto dexpf = [&](float xf) -> float {
        double x = (double)xf;
        double t = __fma_rn(x, INVLN2_32, BIGMAGIC);
        int    k = __double2loint(t);
        double fk = t - BIGMAGIC;
        double r = __fma_rn(fk, -LN2_32HI, x);
        r        = __fma_rn(fk, -LN2_32LO, r);
        double q = __fma_rn(1.0 / 24.0, r, 1.0 / 6.0);
        q = __fma_rn(q, r, 0.5);
        q = __fma_rn(q, r, 1.0);
        q = __fma_rn(q, r, 1.0);
        double v = q * s_exptab[k & 31];
        long long bits = __double_as_longlong(v) + ((long long)(k >> 5) << 52);
        return (float)__longlong_as_double(bits);
    };

    // Reference (XLA:CPU, no contraction):
    //   e = fsub(fmul(s, c), fmul(m1, n3)), n3 = -cos (shared product)
    auto log_ratio = [&](float s3, float n3, float m1, float c1, float c2) -> float {
        const float pm = 1e-6f;
        const float t  = __fmul_rn(m1, n3);
        float e1 = __fsub_rn(__fmul_rn(s3, c1), t);
        float e2 = __fsub_rn(__fmul_rn(s3, c2), t);
        float la = dlogf(fmaxf(fabsf(e1), pm));
        float lb = dlogf(fmaxf(fabsf(e2), pm));
        float v  = __fsub_rn(la, lb);
        return fminf(fmaxf(v, -10.0f), 10.0f);
    };

    int tid = blockIdx.x * blockDim.x + threadIdx.x;
    if (tid >= NCELL) return;

    int cx = tid % LWD;
    int t  = tid / LWD;
    int cy = t % LHD;
    int b  = t / LHD;

    const float fx = intr[b * 9 + 0];
    const float bx = intr[b * 9 + 2];
    const float fy = intr[b * 9 + 4];
    const float by = intr[b * 9 + 5];

    const int y0 = cy * 4;   // block top row  (== yy0 - 2)
    const int x0 = cx * 4;   // block left col (== xx0 - 2)

    const float* __restrict__ angh = ang + (size_t)(b * 2 + 0) * HD * WD;
    const float* __restrict__ angv = ang + (size_t)(b * 2 + 1) * HD * WD;

    float lh[4][3];
    float lv[3][4];

    #pragma unroll
    for (int r = 0; r < 4; ++r) {
        const int y = y0 + r;
        const float yf = (float)y;
        const float ty  = __fdiv_rn(__fsub_rn(yf, by), fy);
        const float a1  = __fadd_rn(__fmul_rn(ty, ty), 1.0f);
        const float v1  = -ty;
        const float v2  = -__fdiv_rn(__fsub_rn(__fadd_rn(yf, 1.0f), by), fy);
        #pragma unroll
        for (int c = 0; c < 4; ++c) {
            const int x = x0 + c;
            const float xf = (float)x;
            const float tx = __fdiv_rn(__fsub_rn(xf, bx), fx);
            if (c < 3) {
                const float b1 = -tx;
                const float b2 = -__fdiv_rn(__fsub_rn(__fadd_rn(xf, 1.0f), bx), fx);
                float s, co;
                dsincosf(angh[(size_t)y * WD + x], &s, &co);
                lh[r][c] = log_ratio(s, -co, a1, b1, b2);
            }
            if (r < 3) {
                const float u1 = __fadd_rn(__fmul_rn(tx, tx), 1.0f);
                float s, co;
                dsincosf(angv[(size_t)y * WD + x], &s, &co);
                lv[r][c] = log_ratio(s, -co, u1, v1, v2);
            }
        }
    }

    // d[row][col]: row = mm+2, col = nn+2  -> pixel (y0+row, x0+col)
    float d[4][4];
    d[2][2] = dlogf(depth[tid]);

    #pragma unroll
    for (int m = 0; m < 4; ++m) {
        #pragma unroll
        for (int n = 0; n < 4; ++n) {
            if (m == 0 && n == 0) continue;
            const int mm = (m & 1) ? -((m + 1) >> 1) : (m >> 1);
            const int nn = (n & 1) ? -((n + 1) >> 1) : (n >> 1);

            int lx1 = 0, ly1 = 0, ch1 = 0, dx1 = 0, dy1 = 0;
            int lx2 = 0, ly2 = 0, ch2 = 0, dx2 = 0, dy2 = 0;
            float s1 = 0.0f, s2 = 0.0f;
            const bool has1 = (nn != 0);
            const bool has2 = (mm != 0);
            if (nn < 0)      { lx1 = nn;     ly1 = mm; ch1 = 0; dx1 = nn + 1; dy1 = mm;     s1 = -1.0f; }
            else if (nn > 0) { lx1 = nn - 1; ly1 = mm; ch1 = 0; dx1 = nn - 1; dy1 = mm;     s1 =  1.0f; }
            if (mm > 0)      { lx2 = nn; ly2 = mm - 1; ch2 = 1; dx2 = nn;     dy2 = mm - 1; s2 =  1.0f; }
            else if (mm < 0) { lx2 = nn; ly2 = mm;     ch2 = 1; dx2 = nn;     dy2 = mm + 1; s2 = -1.0f; }
            if (!has1) { lx1 = lx2; ly1 = ly2; ch1 = ch2; dx1 = dx2; dy1 = dy2; s1 = s2; }
            if (!has2) { lx2 = lx1; ly2 = ly1; ch2 = ch1; dx2 = dx1; dy2 = dy1; s2 = s1; }

            const float l1 = (ch1 == 0) ? lh[ly1 + 2][lx1 + 2] : lv[ly1 + 2][lx1 + 2];
            const float l2 = (ch2 == 0) ? lh[ly2 + 2][lx2 + 2] : lv[ly2 + 2][lx2 + 2];

            float acc = __fadd_rn(d[dy1 + 2][dx1 + 2], __fmul_rn(s1, l1));
            acc = __fadd_rn(acc, d[dy2 + 2][dx2 + 2]);
            acc = __fadd_rn(acc, __fmul_rn(s2, l2));
            d[mm + 2][nn + 2] = __fmul_rn(acc, 0.5f);
        }
    }

    #pragma unroll
    for (int r = 0; r < 4; ++r) {
        const int y = y0 + r;
        float4 o;
        o.x = dexpf(d[r][0]);
        o.y = dexpf(d[r][1]);
        o.z = dexpf(d[r][2]);
        o.w = dexpf(d[r][3]);
        *reinterpret_cast<float4*>(&out[((size_t)b * HD + y) * WD + x0]) = o;
    }
}

extern "C" void kernel_launch(void* const* d_in, const int* in_sizes, int n_in,
                              void* d_out, int out_size)
{
    const float* depth = (const float*)d_in[0];
    const float* ang   = (const float*)d_in[1];
    const float* intr  = (const float*)d_in[2];
    float* out = (float*)d_out;

    const int threads = 128;
    const int blocks = (NCELL + threads - 1) / threads;
    sno_kernel<<<blocks, threads>>>(depth, ang, intr, out);
}

// round 7
// speedup vs baseline: 5.0996x; 2.3107x over previous
#include <cuda_runtime.h>
#include <cuda_bf16.h>

// Problem constants (B, H, W, SCALE) = (8, 384, 1280, 2)
#define BD   8
#define HD   384
#define WD   1280
#define LHD  (HD / 4)    // 96
#define LWD  (WD / 4)    // 320
#define NCELL (BD * LHD * LWD)  // 245760

// ---- constants ----
#define BIGMAGIC  6755399441055744.0          // 2^52 + 2^51
#define INVPIO2   6.36619772367581382433e-01
#define PIO2_1    1.57079632673412561417e+00  // 33-bit head of pi/2
#define PIO2_1T   6.07710050650619224932e-11  // tail

// Fused sin/cos: double-internal, error ~2^-50. Float-rounded results
// bit-match the aarch64 glibc (double-internal) reference sinf/cosf.
// ONLY sin/cos need this fidelity: they feed the cancellation
// e = s*c1 - a1*cos which is amplified by 1/|e| through log.
__device__ __forceinline__ void dsincosf(float xf, float* sf, float* cf)
{
    double x = (double)xf;
    double t = __fma_rn(x, INVPIO2, BIGMAGIC);
    int    k = __double2loint(t);
    double fk = t - BIGMAGIC;
    double r = __fma_rn(fk, -PIO2_1,  x);
    r        = __fma_rn(fk, -PIO2_1T, r);
    double z = r * r;
    // FDLIBM sin poly (degree 13)
    double sp = __fma_rn(1.58969099521155010221e-10, z, -2.50507602534068634195e-08);
    sp = __fma_rn(sp, z,  2.75573137070700676789e-06);
    sp = __fma_rn(sp, z, -1.98412698298579493134e-04);
    sp = __fma_rn(sp, z,  8.33333333332248946124e-03);
    sp = __fma_rn(sp, z, -1.66666666666666324348e-01);
    double s = __fma_rn(sp * z, r, r);
    // FDLIBM cos poly (degree 12)
    double cp = __fma_rn(-1.13596475577881948265e-11, z, 2.08757232129817482790e-09);
    cp = __fma_rn(cp, z, -2.75573143513906633035e-07);
    cp = __fma_rn(cp, z,  2.48015872894767294178e-05);
    cp = __fma_rn(cp, z, -1.38888888888741095749e-03);
    cp = __fma_rn(cp, z,  4.16666666666666019037e-02);
    cp = __fma_rn(cp, z, -0.5);
    double c = __fma_rn(cp, z, 1.0);
    // Round to float FIRST, then swap/sign-flip in 32-bit (bit-identical:
    // fl(-x) == -fl(x)); keeps selects off the FP64 pipe.
    float sfl = (float)s;
    float cfl = (float)c;
    float s0 = (k & 1) ? cfl : sfl;
    float c0 = (k & 1) ? sfl : cfl;
    if (k & 2)       s0 = __int_as_float(__float_as_int(s0) ^ 0x80000000);
    if ((k + 1) & 2) c0 = __int_as_float(__float_as_int(c0) ^ 0x80000000);
    *sf = s0;
    *cf = c0;
}

// log/exp outputs are NOT amplification-critical (enter d-chain additively,
// error <= ~1e-6 abs propagates linearly, tolerance 1e-3) -> fast MUFU path.
__device__ __forceinline__ float flog(float x) { return __logf(x); }
__device__ __forceinline__ float fexp(float x) { return __expf(x); }

// e1/e2 must stay float-bit-exact to the reference (XLA:CPU, no contraction):
// e = fsub(fmul(s, c), fmul(m1, n3)), n3 = -cos (shared product)
__device__ __forceinline__ float log_ratio(float s3, float n3,
                                           float m1, float c1, float c2)
{
    const float pm = 1e-6f;
    const float t  = __fmul_rn(m1, n3);
    float e1 = __fsub_rn(__fmul_rn(s3, c1), t);
    float e2 = __fsub_rn(__fmul_rn(s3, c2), t);
    float la = flog(fmaxf(fabsf(e1), pm));
    float lb = flog(fmaxf(fabsf(e2), pm));
    float v  = __fsub_rn(la, lb);
    return fminf(fmaxf(v, -10.0f), 10.0f);
}

__global__ __launch_bounds__(256)
void sno_kernel(const float* __restrict__ depth,
                const float* __restrict__ ang,
                const float* __restrict__ intr,
                float* __restrict__ out)
{
    int tid = blockIdx.x * blockDim.x + threadIdx.x;
    if (tid >= NCELL) return;

    int cx = tid % LWD;
    int t  = tid / LWD;
    int cy = t % LHD;
    int b  = t / LHD;

    const float fx = intr[b * 9 + 0];
    const float bx = intr[b * 9 + 2];
    const float fy = intr[b * 9 + 4];
    const float by = intr[b * 9 + 5];

    const int y0 = cy * 4;   // block top row  (== yy0 - 2)
    const int x0 = cx * 4;   // block left col (== xx0 - 2)

    const float* __restrict__ angh = ang + (size_t)(b * 2 + 0) * HD * WD;
    const float* __restrict__ angv = ang + (size_t)(b * 2 + 1) * HD * WD;

    float lh[4][3];
    float lv[3][4];

    #pragma unroll
    for (int r = 0; r < 4; ++r) {
        const int y = y0 + r;
        const float yf = (float)y;
        const float ty  = __fdiv_rn(__fsub_rn(yf, by), fy);
        const float a1  = __fadd_rn(__fmul_rn(ty, ty), 1.0f);
        const float v1  = -ty;
        const float v2  = -__fdiv_rn(__fsub_rn(__fadd_rn(yf, 1.0f), by), fy);
        #pragma unroll
        for (int c = 0; c < 4; ++c) {
            const int x = x0 + c;
            const float xf = (float)x;
            const float tx = __fdiv_rn(__fsub_rn(xf, bx), fx);
            if (c < 3) {
                const float b1 = -tx;
                const float b2 = -__fdiv_rn(__fsub_rn(__fadd_rn(xf, 1.0f), bx), fx);
                float s, co;
                dsincosf(angh[(size_t)y * WD + x], &s, &co);
                lh[r][c] = log_ratio(s, -co, a1, b1, b2);
            }
            if (r < 3) {
                const float u1 = __fadd_rn(__fmul_rn(tx, tx), 1.0f);
                float s, co;
                dsincosf(angv[(size_t)y * WD + x], &s, &co);
                lv[r][c] = log_ratio(s, -co, u1, v1, v2);
            }
        }
    }

    // d[row][col]: row = mm+2, col = nn+2  -> pixel (y0+row, x0+col)
    float d[4][4];
    d[2][2] = flog(depth[tid]);

    #pragma unroll
    for (int m = 0; m < 4; ++m) {
        #pragma unroll
        for (int n = 0; n < 4; ++n) {
            if (m == 0 && n == 0) continue;
            const int mm = (m & 1) ? -((m + 1) >> 1) : (m >> 1);
            const int nn = (n & 1) ? -((n + 1) >> 1) : (n >> 1);

            int lx1 = 0, ly1 = 0, ch1 = 0, dx1 = 0, dy1 = 0;
            int lx2 = 0, ly2 = 0, ch2 = 0, dx2 = 0, dy2 = 0;
            float s1 = 0.0f, s2 = 0.0f;
            const bool has1 = (nn != 0);
            const bool has2 = (mm != 0);
            if (nn < 0)      { lx1 = nn;     ly1 = mm; ch1 = 0; dx1 = nn + 1; dy1 = mm;     s1 = -1.0f; }
            else if (nn > 0) { lx1 = nn - 1; ly1 = mm; ch1 = 0; dx1 = nn - 1; dy1 = mm;     s1 =  1.0f; }
            if (mm > 0)      { lx2 = nn; ly2 = mm - 1; ch2 = 1; dx2 = nn;     dy2 = mm - 1; s2 =  1.0f; }
            else if (mm < 0) { lx2 = nn; ly2 = mm;     ch2 = 1; dx2 = nn;     dy2 = mm + 1; s2 = -1.0f; }
            if (!has1) { lx1 = lx2; ly1 = ly2; ch1 = ch2; dx1 = dx2; dy1 = dy2; s1 = s2; }
            if (!has2) { lx2 = lx1; ly2 = ly1; ch2 = ch1; dx2 = dx1; dy2 = dy1; s2 = s1; }

            const float l1 = (ch1 == 0) ? lh[ly1 + 2][lx1 + 2] : lv[ly1 + 2][lx1 + 2];
            const float l2 = (ch2 == 0) ? lh[ly2 + 2][lx2 + 2] : lv[ly2 + 2][lx2 + 2];

            float acc = __fadd_rn(d[dy1 + 2][dx1 + 2], __fmul_rn(s1, l1));
            acc = __fadd_rn(acc, d[dy2 + 2][dx2 + 2]);
            acc = __fadd_rn(acc, __fmul_rn(s2, l2));
            d[mm + 2][nn + 2] = __fmul_rn(acc, 0.5f);
        }
    }

    #pragma unroll
    for (int r = 0; r < 4; ++r) {
        const int y = y0 + r;
        float4 o;
        o.x = fexp(d[r][0]);
        o.y = fexp(d[r][1]);
        o.z = fexp(d[r][2]);
        o.w = fexp(d[r][3]);
        *reinterpret_cast<float4*>(&out[((size_t)b * HD + y) * WD + x0]) = o;
    }
}

extern "C" void kernel_launch(void* const* d_in, const int* in_sizes, int n_in,
                              void* d_out, int out_size)
{
    const float* depth = (const float*)d_in[0];
    const float* ang   = (const float*)d_in[1];
    const float* intr  = (const float*)d_in[2];
    float* out = (float*)d_out;

    const int threads = 256;
    const int blocks = (NCELL + threads - 1) / threads;
    sno_kernel<<<blocks, threads>>>(depth, ang, intr, out);
}

// round 8
// speedup vs baseline: 42.6976x; 8.3727x over previous
#include <cuda_runtime.h>
#include <cuda_bf16.h>

// Problem constants (B, H, W, SCALE) = (8, 384, 1280, 2)
#define BD   8
#define HD   384
#define WD   1280
#define LHD  (HD / 4)    // 96
#define LWD  (WD / 4)    // 320
#define NCELL (BD * LHD * LWD)  // 245760

// ---------------------------------------------------------------------------
// float-float sincos, total abs error ~2^-37: float rounding matches the
// reference's double-internal sinf/cosf except ~2^-12 of calls (1-ulp diffs
// at random pixels -> negligible after amplification analysis).
// Entirely on the FMA pipe -- zero FP64.
// ---------------------------------------------------------------------------

// branch-free TwoSum: s + e == a + b exactly
__device__ __forceinline__ void twosum(float a, float b, float& s, float& e)
{
    s = __fadd_rn(a, b);
    float bb = __fsub_rn(s, a);
    e = __fadd_rn(__fsub_rn(a, __fsub_rn(s, bb)), __fsub_rn(b, bb));
}

__device__ __forceinline__ void ffsincos(float x, float* so, float* co)
{
    const float INVPIO2F = 0.636619772367581343f;
    const float MAGICF   = 12582912.0f;            // 2^23 + 2^22
    // pi/2 = PH + PM + PL (+ ~2^-47): PH, PM have 11-bit mantissas so
    // fk*PH, fk*PM are EXACT float products for |fk| <= 8.
    const float PH = 1.5703125f;                   // 11-bit
    const float PM = 4.83751297e-4f;               // 2029/2^22, 11-bit
    const float PL = 7.54978995e-8f;

    float t  = __fmaf_rn(x, INVPIO2F, MAGICF);
    float fk = __fsub_rn(t, MAGICF);
    int   ki = (int)fk;

    float a  = __fmaf_rn(fk, -PH, x);              // exact (Sterbenz)
    float p2 = __fmul_rn(fk, PM);                  // exact
    float s1, e1; twosum(a, -p2, s1, e1);
    float rl0 = __fmaf_rn(fk, -PL, e1);
    float rh, rl; twosum(s1, rl0, rh, rl);         // r = rh + rl, err ~2^-45

    // z = r^2 as ds
    float zh  = __fmul_rn(rh, rh);
    float ze  = __fmaf_rn(rh, rh, -zh);
    float zl  = __fmaf_rn(__fadd_rn(rh, rh), rl, ze);

    // ---- sin(r) = r + r*z*sp(z), FDLIBM coefficients ----
    const float S1H = -0.166666671633720398f, S1L = 4.9670572e-9f;
    const float S2H =  8.33333376795053482e-3f, S2L = -4.3462805e-10f;
    const float S3F = -1.98412698298579493e-4f;
    const float S4F =  2.75573137070700677e-6f;
    const float S5F = -2.50507602534068634e-8f;
    const float S6F =  1.58969099521155010e-10f;

    float tl = __fmaf_rn(zh, S6F, S5F);
    tl = __fmaf_rn(zh, tl, S4F);
    tl = __fmaf_rn(zh, tl, S3F);
    float p  = __fmul_rn(zh, tl);
    float h2 = __fadd_rn(S2H, p);                  // Fast2Sum: |S2H| >= |p|
    float l2 = __fadd_rn(__fsub_rn(S2H, h2), p);
    l2 = __fadd_rn(l2, S2L);
    l2 = __fmaf_rn(zl, tl, l2);
    float qh = __fmul_rn(zh, h2);
    float ql = __fmaf_rn(zh, h2, -qh);
    ql = __fmaf_rn(zh, l2, ql);
    ql = __fmaf_rn(zl, h2, ql);
    float h1 = __fadd_rn(S1H, qh);                 // Fast2Sum: |S1H| >= |qh|
    float t1 = __fadd_rn(__fsub_rn(S1H, h1), qh);
    float l1 = __fadd_rn(__fadd_rn(t1, S1L), ql);
    float uh = __fmul_rn(zh, h1);
    float ul = __fmaf_rn(zh, h1, -uh);
    ul = __fmaf_rn(zh, l1, ul);
    ul = __fmaf_rn(zl, h1, ul);
    float Th = __fmul_rn(rh, uh);
    float Tl = __fmaf_rn(rh, uh, -Th);
    Tl = __fmaf_rn(rh, ul, Tl);
    Tl = __fmaf_rn(rl, uh, Tl);
    float sh = __fadd_rn(rh, Th);                  // Fast2Sum: |rh| >= |Th|
    float st = __fadd_rn(__fsub_rn(rh, sh), Th);
    float sl = __fadd_rn(__fadd_rn(st, Tl), rl);
    float s_pre = __fadd_rn(sh, sl);

    // ---- cos(r) = 1 + z*(-1/2 + z*cp(z)) ----
    const float C1H = 4.16666679084301e-2f, C1L = -1.2417635e-9f;
    const float C2H = -1.38888892255723476e-3f, C2L = 3.3669824e-11f;
    const float C3F =  2.48015872894767294e-5f;
    const float C4F = -2.75573143513906633e-7f;
    const float C5F =  2.08757232129817483e-9f;
    const float C6F = -1.13596475577881948e-11f;

    float tc = __fmaf_rn(zh, C6F, C5F);
    tc = __fmaf_rn(zh, tc, C4F);
    tc = __fmaf_rn(zh, tc, C3F);
    float pc  = __fmul_rn(zh, tc);
    float hc2 = __fadd_rn(C2H, pc);                // Fast2Sum ok
    float lc2 = __fadd_rn(__fsub_rn(C2H, hc2), pc);
    lc2 = __fadd_rn(lc2, C2L);
    lc2 = __fmaf_rn(zl, tc, lc2);
    float qch = __fmul_rn(zh, hc2);
    float qcl = __fmaf_rn(zh, hc2, -qch);
    qcl = __fmaf_rn(zh, lc2, qcl);
    qcl = __fmaf_rn(zl, hc2, qcl);
    float hc1 = __fadd_rn(C1H, qch);               // Fast2Sum ok
    float tc1 = __fadd_rn(__fsub_rn(C1H, hc1), qch);
    float lc1 = __fadd_rn(__fadd_rn(tc1, C1L), qcl);
    float wh = __fmul_rn(zh, hc1);
    float wl = __fmaf_rn(zh, hc1, -wh);
    wl = __fmaf_rn(zh, lc1, wl);
    wl = __fmaf_rn(zl, hc1, wl);
    float gh = __fadd_rn(-0.5f, wh);               // Fast2Sum: 0.5 >= |wh|
    float gt = __fadd_rn(__fsub_rn(-0.5f, gh), wh);
    float gl = __fadd_rn(gt, wl);
    float Uh = __fmul_rn(zh, gh);
    float Ul = __fmaf_rn(zh, gh, -Uh);
    Ul = __fmaf_rn(zh, gl, Ul);
    Ul = __fmaf_rn(zl, gh, Ul);
    float ch_ = __fadd_rn(1.0f, Uh);               // Fast2Sum: 1 >= |Uh|
    float ct_ = __fadd_rn(__fsub_rn(1.0f, ch_), Uh);
    float cl_ = __fadd_rn(ct_, Ul);
    float c_pre = __fadd_rn(ch_, cl_);

    // quadrant fix in float/int domain (exact)
    float s0 = (ki & 1) ? c_pre : s_pre;
    float c0 = (ki & 1) ? s_pre : c_pre;
    if (ki & 2)       s0 = __int_as_float(__float_as_int(s0) ^ 0x80000000);
    if ((ki + 1) & 2) c0 = __int_as_float(__float_as_int(c0) ^ 0x80000000);
    *so = s0;
    *co = c0;
}

// log/exp outputs are NOT amplification-critical -> fast MUFU path (proven R7).
__device__ __forceinline__ float flog(float x) { return __logf(x); }
__device__ __forceinline__ float fexp(float x) { return __expf(x); }

// e1/e2 must stay float-bit-exact to the reference (XLA:CPU, no contraction):
// e = fsub(fmul(s, c), fmul(m1, n3)), n3 = -cos (shared product)
__device__ __forceinline__ float log_ratio(float s3, float n3,
                                           float m1, float c1, float c2)
{
    const float pm = 1e-6f;
    const float t  = __fmul_rn(m1, n3);
    float e1 = __fsub_rn(__fmul_rn(s3, c1), t);
    float e2 = __fsub_rn(__fmul_rn(s3, c2), t);
    float la = flog(fmaxf(fabsf(e1), pm));
    float lb = flog(fmaxf(fabsf(e2), pm));
    float v  = __fsub_rn(la, lb);
    return fminf(fmaxf(v, -10.0f), 10.0f);
}

__global__ __launch_bounds__(256)
void sno_kernel(const float* __restrict__ depth,
                const float* __restrict__ ang,
                const float* __restrict__ intr,
                float* __restrict__ out)
{
    int tid = blockIdx.x * blockDim.x + threadIdx.x;
    if (tid >= NCELL) return;

    int cx = tid % LWD;
    int t  = tid / LWD;
    int cy = t % LHD;
    int b  = t / LHD;

    const float fx = intr[b * 9 + 0];
    const float bx = intr[b * 9 + 2];
    const float fy = intr[b * 9 + 4];
    const float by = intr[b * 9 + 5];

    const int y0 = cy * 4;   // block top row  (== yy0 - 2)
    const int x0 = cx * 4;   // block left col (== xx0 - 2)

    const float* __restrict__ angh = ang + (size_t)(b * 2 + 0) * HD * WD;
    const float* __restrict__ angv = ang + (size_t)(b * 2 + 1) * HD * WD;

    float lh[4][3];
    float lv[3][4];

    #pragma unroll
    for (int r = 0; r < 4; ++r) {
        const int y = y0 + r;
        const float yf = (float)y;
        const float ty  = __fdiv_rn(__fsub_rn(yf, by), fy);
        const float a1  = __fadd_rn(__fmul_rn(ty, ty), 1.0f);
        const float v1  = -ty;
        const float v2  = -__fdiv_rn(__fsub_rn(__fadd_rn(yf, 1.0f), by), fy);
        #pragma unroll
        for (int c = 0; c < 4; ++c) {
            const int x = x0 + c;
            const float xf = (float)x;
            const float tx = __fdiv_rn(__fsub_rn(xf, bx), fx);
            if (c < 3) {
                const float b1 = -tx;
                const float b2 = -__fdiv_rn(__fsub_rn(__fadd_rn(xf, 1.0f), bx), fx);
                float s, co;
                ffsincos(angh[(size_t)y * WD + x], &s, &co);
                lh[r][c] = log_ratio(s, -co, a1, b1, b2);
            }
            if (r < 3) {
                const float u1 = __fadd_rn(__fmul_rn(tx, tx), 1.0f);
                float s, co;
                ffsincos(angv[(size_t)y * WD + x], &s, &co);
                lv[r][c] = log_ratio(s, -co, u1, v1, v2);
            }
        }
    }

    // d[row][col]: row = mm+2, col = nn+2  -> pixel (y0+row, x0+col)
    float d[4][4];
    d[2][2] = flog(depth[tid]);

    #pragma unroll
    for (int m = 0; m < 4; ++m) {
        #pragma unroll
        for (int n = 0; n < 4; ++n) {
            if (m == 0 && n == 0) continue;
            const int mm = (m & 1) ? -((m + 1) >> 1) : (m >> 1);
            const int nn = (n & 1) ? -((n + 1) >> 1) : (n >> 1);

            int lx1 = 0, ly1 = 0, ch1 = 0, dx1 = 0, dy1 = 0;
            int lx2 = 0, ly2 = 0, ch2 = 0, dx2 = 0, dy2 = 0;
            float s1 = 0.0f, s2 = 0.0f;
            const bool has1 = (nn != 0);
            const bool has2 = (mm != 0);
            if (nn < 0)      { lx1 = nn;     ly1 = mm; ch1 = 0; dx1 = nn + 1; dy1 = mm;     s1 = -1.0f; }
            else if (nn > 0) { lx1 = nn - 1; ly1 = mm; ch1 = 0; dx1 = nn - 1; dy1 = mm;     s1 =  1.0f; }
            if (mm > 0)      { lx2 = nn; ly2 = mm - 1; ch2 = 1; dx2 = nn;     dy2 = mm - 1; s2 =  1.0f; }
            else if (mm < 0) { lx2 = nn; ly2 = mm;     ch2 = 1; dx2 = nn;     dy2 = mm + 1; s2 = -1.0f; }
            if (!has1) { lx1 = lx2; ly1 = ly2; ch1 = ch2; dx1 = dx2; dy1 = dy2; s1 = s2; }
            if (!has2) { lx2 = lx1; ly2 = ly1; ch2 = ch1; dx2 = dx1; dy2 = dy1; s2 = s1; }

            const float l1 = (ch1 == 0) ? lh[ly1 + 2][lx1 + 2] : lv[ly1 + 2][lx1 + 2];
            const float l2 = (ch2 == 0) ? lh[ly2 + 2][lx2 + 2] : lv[ly2 + 2][lx2 + 2];

            float acc = __fadd_rn(d[dy1 + 2][dx1 + 2], __fmul_rn(s1, l1));
            acc = __fadd_rn(acc, d[dy2 + 2][dx2 + 2]);
            acc = __fadd_rn(acc, __fmul_rn(s2, l2));
            d[mm + 2][nn + 2] = __fmul_rn(acc, 0.5f);
        }
    }

    #pragma unroll
    for (int r = 0; r < 4; ++r) {
        const int y = y0 + r;
        float4 o;
        o.x = fexp(d[r][0]);
        o.y = fexp(d[r][1]);
        o.z = fexp(d[r][2]);
        o.w = fexp(d[r][3]);
        *reinterpret_cast<float4*>(&out[((size_t)b * HD + y) * WD + x0]) = o;
    }
}

extern "C" void kernel_launch(void* const* d_in, const int* in_sizes, int n_in,
                              void* d_out, int out_size)
{
    const float* depth = (const float*)d_in[0];
    const float* ang   = (const float*)d_in[1];
    const float* intr  = (const float*)d_in[2];
    float* out = (float*)d_out;

    const int threads = 256;
    const int blocks = (NCELL + threads - 1) / threads;
    sno_kernel<<<blocks, threads>>>(depth, ang, intr, out);
}

// round 9
// speedup vs baseline: 51.1871x; 1.1988x over previous
#include <cuda_runtime.h>
#include <cuda_bf16.h>

// Problem constants (B, H, W, SCALE) = (8, 384, 1280, 2)
#define BD   8
#define HD   384
#define WD   1280
#define LHD  (HD / 4)    // 96
#define LWD  (WD / 4)    // 320
#define NCELL (BD * LHD * LWD)  // 245760

// ---------------------------------------------------------------------------
// Slimmed float-float sincos, total abs error ~2^-29.5. Calibrated budget:
// amplification A~6e4 (from R1 datapoint) -> contribution ~1e-4 rel_err.
// Entirely FMA-pipe.
// ---------------------------------------------------------------------------
__device__ __forceinline__ void ffsincos(float x, float* so, float* co)
{
    const float INVPIO2F = 0.636619772367581343f;
    const float MAGICF   = 12582912.0f;            // 2^23 + 2^22
    const float PH = 1.5703125f;                   // 11-bit: fk*PH exact
    const float PM = 4.83751297e-4f;               // 11-bit: fk*PM exact
    const float PL = 7.54978995e-8f;

    float t  = __fmaf_rn(x, INVPIO2F, MAGICF);
    float fk = __fsub_rn(t, MAGICF);
    int   ki = (int)fk;

    float a  = __fmaf_rn(fk, -PH, x);              // exact (Sterbenz)
    float p2 = __fmul_rn(fk, PM);                  // exact
    // TwoSum(a, -p2) -> (rh, e1); rl = e1 - fk*PL  (unnormalized ds r)
    float rh = __fsub_rn(a, p2);
    float bb = __fsub_rn(rh, a);
    float e1 = __fadd_rn(__fsub_rn(a, __fsub_rn(rh, bb)), __fsub_rn(-p2, bb));
    float rl = __fmaf_rn(fk, -PL, e1);

    // z = r^2 as ds
    float zh = __fmul_rn(rh, rh);
    float ze = __fmaf_rn(rh, rh, -zh);
    float zl = __fmaf_rn(__fadd_rn(rh, rh), rl, ze);

    // ---- sin(r) = r + r*z*(S1 + z*tail) ; only S1 kept in ds ----
    const float S1H = -0.166666671633720398f, S1L = 4.9670572e-9f;
    float tp = __fmaf_rn(zh, 1.58969099521155010e-10f, -2.50507602534068634e-8f);
    tp = __fmaf_rn(zh, tp,  2.75573137070700677e-6f);
    tp = __fmaf_rn(zh, tp, -1.98412698298579493e-4f);
    tp = __fmaf_rn(zh, tp,  8.33333376795053482e-3f);   // S2 in float tail
    float q  = __fmul_rn(zh, tp);
    float h1 = __fadd_rn(S1H, q);                       // Fast2Sum: |S1H|>=|q|
    float l1 = __fadd_rn(__fadd_rn(__fsub_rn(S1H, h1), q), S1L);
    float uh = __fmul_rn(zh, h1);
    float ul = __fmaf_rn(zh, h1, -uh);
    ul = __fmaf_rn(zh, l1, ul);
    ul = __fmaf_rn(zl, h1, ul);
    float Th = __fmul_rn(rh, uh);
    float Tl = __fmaf_rn(rh, uh, -Th);
    Tl = __fmaf_rn(rh, ul, Tl);
    Tl = __fmaf_rn(rl, uh, Tl);
    float sh = __fadd_rn(rh, Th);                       // Fast2Sum: |rh|>=|Th|
    float st = __fadd_rn(__fsub_rn(rh, sh), Th);
    float s_pre = __fadd_rn(sh, __fadd_rn(__fadd_rn(st, Tl), rl));

    // ---- cos(r) = 1 + z*(-1/2 + z*(C1 + z*tail)) ; only C1 in ds ----
    const float C1H = 4.16666679084301e-2f, C1L = -1.2417635e-9f;
    float tc = __fmaf_rn(zh, -1.13596475577881948e-11f, 2.08757232129817483e-9f);
    tc = __fmaf_rn(zh, tc, -2.75573143513906633e-7f);
    tc = __fmaf_rn(zh, tc,  2.48015872894767294e-5f);
    tc = __fmaf_rn(zh, tc, -1.38888892255723476e-3f);   // C2 in float tail
    float qc = __fmul_rn(zh, tc);
    float hc = __fadd_rn(C1H, qc);                      // Fast2Sum: |C1H|>=|qc|
    float lc = __fadd_rn(__fadd_rn(__fsub_rn(C1H, hc), qc), C1L);
    float wh = __fmul_rn(zh, hc);
    float wl = __fmaf_rn(zh, hc, -wh);
    wl = __fmaf_rn(zh, lc, wl);
    wl = __fmaf_rn(zl, hc, wl);
    float gh = __fadd_rn(-0.5f, wh);                    // Fast2Sum: 0.5>=|wh|
    float gl = __fadd_rn(__fadd_rn(__fsub_rn(-0.5f, gh), wh), wl);
    float Uh = __fmul_rn(zh, gh);
    float Ul = __fmaf_rn(zh, gh, -Uh);
    Ul = __fmaf_rn(zh, gl, Ul);
    Ul = __fmaf_rn(zl, gh, Ul);
    float ch_ = __fadd_rn(1.0f, Uh);                    // Fast2Sum: 1>=|Uh|
    float c_pre = __fadd_rn(ch_, __fadd_rn(__fadd_rn(__fsub_rn(1.0f, ch_), Uh), Ul));

    // quadrant fix (exact, float/int domain)
    float s0 = (ki & 1) ? c_pre : s_pre;
    float c0 = (ki & 1) ? s_pre : c_pre;
    if (ki & 2)       s0 = __int_as_float(__float_as_int(s0) ^ 0x80000000);
    if ((ki + 1) & 2) c0 = __int_as_float(__float_as_int(c0) ^ 0x80000000);
    *so = s0;
    *co = c0;
}

// log/exp outputs are NOT amplification-critical -> MUFU (proven R7/R8).
__device__ __forceinline__ float flog(float x) { return __logf(x); }
__device__ __forceinline__ float fexp(float x) { return __expf(x); }

// e1/e2 float-bit-exact to reference (XLA:CPU, no contraction):
// e = fsub(fmul(s, c), fmul(m1, n3)), n3 = -cos (shared product)
__device__ __forceinline__ float log_ratio(float s3, float n3,
                                           float m1, float c1, float c2)
{
    const float pm = 1e-6f;
    const float t  = __fmul_rn(m1, n3);
    float e1 = __fsub_rn(__fmul_rn(s3, c1), t);
    float e2 = __fsub_rn(__fmul_rn(s3, c2), t);
    float la = flog(fmaxf(fabsf(e1), pm));
    float lb = flog(fmaxf(fabsf(e2), pm));
    float v  = __fsub_rn(la, lb);
    return fminf(fmaxf(v, -10.0f), 10.0f);
}

__global__ __launch_bounds__(256)
void sno_kernel(const float* __restrict__ depth,
                const float* __restrict__ ang,
                const float* __restrict__ intr,
                float* __restrict__ out)
{
    int tid = blockIdx.x * blockDim.x + threadIdx.x;   // grid exactly covers NCELL

    int cx = tid % LWD;
    int t  = tid / LWD;
    int cy = t % LHD;
    int b  = t / LHD;

    const float fx = intr[b * 9 + 0];
    const float bx = intr[b * 9 + 2];
    const float fy = intr[b * 9 + 4];
    const float by = intr[b * 9 + 5];

    const int y0 = cy * 4;   // block top row  (== yy0 - 2)
    const int x0 = cx * 4;   // block left col (== xx0 - 2)

    const float* __restrict__ angh = ang + (size_t)(b * 2 + 0) * HD * WD;
    const float* __restrict__ angv = ang + (size_t)(b * 2 + 1) * HD * WD;

    // Hoisted per-row/per-column geometry. Bit-exact reuse:
    //   b2 at col c == -tx[c+1], v2 at row r == -ty[r+1] (identical fp exprs)
    float tx[4], ty[4], a1[4], u1[4];
    #pragma unroll
    for (int i = 0; i < 4; ++i) {
        const float xf = (float)(x0 + i);
        const float yf = (float)(y0 + i);
        tx[i] = __fdiv_rn(__fsub_rn(xf, bx), fx);
        ty[i] = __fdiv_rn(__fsub_rn(yf, by), fy);
        a1[i] = __fadd_rn(__fmul_rn(ty[i], ty[i]), 1.0f);
        u1[i] = __fadd_rn(__fmul_rn(tx[i], tx[i]), 1.0f);
    }

    float lh[4][3];
    float lv[3][4];

    #pragma unroll
    for (int r = 0; r < 4; ++r) {
        const float4 hr = *reinterpret_cast<const float4*>(
            angh + (size_t)(y0 + r) * WD + x0);
        const float hv[3] = {hr.x, hr.y, hr.z};
        #pragma unroll
        for (int c = 0; c < 3; ++c) {
            float s, co;
            ffsincos(hv[c], &s, &co);
            lh[r][c] = log_ratio(s, -co, a1[r], -tx[c], -tx[c + 1]);
        }
        if (r < 3) {
            const float4 vr = *reinterpret_cast<const float4*>(
                angv + (size_t)(y0 + r) * WD + x0);
            const float vv[4] = {vr.x, vr.y, vr.z, vr.w};
            #pragma unroll
            for (int c = 0; c < 4; ++c) {
                float s, co;
                ffsincos(vv[c], &s, &co);
                lv[r][c] = log_ratio(s, -co, u1[c], -ty[r], -ty[r + 1]);
            }
        }
    }

    // d[row][col]: row = mm+2, col = nn+2  -> pixel (y0+row, x0+col)
    float d[4][4];
    d[2][2] = flog(depth[tid]);

    #pragma unroll
    for (int m = 0; m < 4; ++m) {
        #pragma unroll
        for (int n = 0; n < 4; ++n) {
            if (m == 0 && n == 0) continue;
            const int mm = (m & 1) ? -((m + 1) >> 1) : (m >> 1);
            const int nn = (n & 1) ? -((n + 1) >> 1) : (n >> 1);

            int lx1 = 0, ly1 = 0, ch1 = 0, dx1 = 0, dy1 = 0;
            int lx2 = 0, ly2 = 0, ch2 = 0, dx2 = 0, dy2 = 0;
            float s1 = 0.0f, s2 = 0.0f;
            const bool has1 = (nn != 0);
            const bool has2 = (mm != 0);
            if (nn < 0)      { lx1 = nn;     ly1 = mm; ch1 = 0; dx1 = nn + 1; dy1 = mm;     s1 = -1.0f; }
            else if (nn > 0) { lx1 = nn - 1; ly1 = mm; ch1 = 0; dx1 = nn - 1; dy1 = mm;     s1 =  1.0f; }
            if (mm > 0)      { lx2 = nn; ly2 = mm - 1; ch2 = 1; dx2 = nn;     dy2 = mm - 1; s2 =  1.0f; }
            else if (mm < 0) { lx2 = nn; ly2 = mm;     ch2 = 1; dx2 = nn;     dy2 = mm + 1; s2 = -1.0f; }
            if (!has1) { lx1 = lx2; ly1 = ly2; ch1 = ch2; dx1 = dx2; dy1 = dy2; s1 = s2; }
            if (!has2) { lx2 = lx1; ly2 = ly1; ch2 = ch1; dx2 = dx1; dy2 = dy1; s2 = s1; }

            const float l1 = (ch1 == 0) ? lh[ly1 + 2][lx1 + 2] : lv[ly1 + 2][lx1 + 2];
            const float l2 = (ch2 == 0) ? lh[ly2 + 2][lx2 + 2] : lv[ly2 + 2][lx2 + 2];

            float acc = __fadd_rn(d[dy1 + 2][dx1 + 2], __fmul_rn(s1, l1));
            acc = __fadd_rn(acc, d[dy2 + 2][dx2 + 2]);
            acc = __fadd_rn(acc, __fmul_rn(s2, l2));
            d[mm + 2][nn + 2] = __fmul_rn(acc, 0.5f);
        }
    }

    #pragma unroll
    for (int r = 0; r < 4; ++r) {
        const int y = y0 + r;
        float4 o;
        o.x = fexp(d[r][0]);
        o.y = fexp(d[r][1]);
        o.z = fexp(d[r][2]);
        o.w = fexp(d[r][3]);
        *reinterpret_cast<float4*>(&out[((size_t)b * HD + y) * WD + x0]) = o;
    }
}

extern "C" void kernel_launch(void* const* d_in, const int* in_sizes, int n_in,
                              void* d_out, int out_size)
{
    const float* depth = (const float*)d_in[0];
    const float* ang   = (const float*)d_in[1];
    const float* intr  = (const float*)d_in[2];
    float* out = (float*)d_out;

    const int threads = 256;
    const int blocks = NCELL / threads;   // exact: 245760 / 256 = 960
    sno_kernel<<<blocks, threads>>>(depth, ang, intr, out);
}

// round 10
// speedup vs baseline: 52.3505x; 1.0227x over previous
#include <cuda_runtime.h>
#include <cuda_bf16.h>

// Problem constants (B, H, W, SCALE) = (8, 384, 1280, 2)
#define BD   8
#define HD   384
#define WD   1280
#define LHD  (HD / 4)    // 96
#define LWD  (WD / 4)    // 320
#define NCELL (BD * LHD * LWD)  // 245760

typedef unsigned long long u64;

// ---- packed f32x2 primitives (sm_100+): per-lane RN, bit-identical to scalar
__device__ __forceinline__ u64 pk2(float lo, float hi) {
    u64 r; asm("mov.b64 %0, {%1, %2};" : "=l"(r) : "f"(lo), "f"(hi)); return r;
}
__device__ __forceinline__ void upk2(u64 v, float& lo, float& hi) {
    asm("mov.b64 {%0, %1}, %2;" : "=f"(lo), "=f"(hi) : "l"(v));
}
__device__ __forceinline__ u64 fma2(u64 a, u64 b, u64 c) {
    u64 d; asm("fma.rn.f32x2 %0, %1, %2, %3;" : "=l"(d) : "l"(a), "l"(b), "l"(c)); return d;
}
__device__ __forceinline__ u64 mul2(u64 a, u64 b) {
    u64 d; asm("mul.rn.f32x2 %0, %1, %2;" : "=l"(d) : "l"(a), "l"(b)); return d;
}
__device__ __forceinline__ u64 add2(u64 a, u64 b) {
    u64 d; asm("add.rn.f32x2 %0, %1, %2;" : "=l"(d) : "l"(a), "l"(b)); return d;
}

// ---------------------------------------------------------------------------
// Packed two-angle float-float sincos. Identical per-lane arithmetic to the
// R9 slim ffsincos (every sub replaced by fma(x,-1,y), exact); abs err
// ~2^-29.5, proven to contribute nothing to rel_err (R8/R9 invariance).
// ---------------------------------------------------------------------------
__device__ __forceinline__ void ffsincos2(float xa, float xb,
                                          float& sA, float& cA,
                                          float& sB, float& cB)
{
    const u64 K_INV  = pk2(0.636619772367581343f, 0.636619772367581343f);
    const u64 K_MAG  = pk2(12582912.0f, 12582912.0f);
    const u64 K_NMAG = pk2(-12582912.0f, -12582912.0f);
    const u64 K_NPH  = pk2(-1.5703125f, -1.5703125f);
    const u64 K_NPM  = pk2(-4.83751297e-4f, -4.83751297e-4f);
    const u64 K_NPL  = pk2(-7.54978995e-8f, -7.54978995e-8f);
    const u64 K_N1   = pk2(-1.0f, -1.0f);

    u64 x = pk2(xa, xb);
    u64 t = fma2(x, K_INV, K_MAG);
    float tlo, thi; upk2(t, tlo, thi);
    int ka = __float_as_int(tlo) - 0x4B400000;   // == (int)fk per lane
    int kb = __float_as_int(thi) - 0x4B400000;
    u64 fk  = add2(t, K_NMAG);                   // exact
    u64 a   = fma2(fk, K_NPH, x);                // exact (Sterbenz)
    u64 p2n = mul2(fk, K_NPM);                   // exact, == -fk*PM
    // TwoSum(a, p2n)
    u64 rh  = add2(a, p2n);
    u64 bb  = fma2(a, K_N1, rh);                 // rh - a
    u64 w1  = fma2(bb, K_N1, rh);                // rh - bb
    u64 w2  = fma2(w1, K_N1, a);                 // a - (rh - bb)
    u64 w3  = fma2(bb, K_N1, p2n);               // p2n - bb
    u64 e1  = add2(w2, w3);
    u64 rl  = fma2(fk, K_NPL, e1);

    u64 zh  = mul2(rh, rh);
    u64 zhn = mul2(zh, K_N1);
    u64 ze  = fma2(rh, rh, zhn);
    u64 zl  = fma2(add2(rh, rh), rl, ze);

    // ---- sin(r) = r + r*z*(S1ds + z*tail) ----
    const u64 KS6  = pk2( 1.58969099521155010e-10f,  1.58969099521155010e-10f);
    const u64 KS5  = pk2(-2.50507602534068634e-8f,  -2.50507602534068634e-8f);
    const u64 KS4  = pk2( 2.75573137070700677e-6f,   2.75573137070700677e-6f);
    const u64 KS3  = pk2(-1.98412698298579493e-4f,  -1.98412698298579493e-4f);
    const u64 KS2  = pk2( 8.33333376795053482e-3f,   8.33333376795053482e-3f);
    const u64 KS1H = pk2(-0.166666671633720398f,    -0.166666671633720398f);
    const u64 KS1L = pk2( 4.9670572e-9f,             4.9670572e-9f);

    u64 tp = fma2(zh, KS6, KS5);
    tp = fma2(zh, tp, KS4);
    tp = fma2(zh, tp, KS3);
    tp = fma2(zh, tp, KS2);
    u64 q  = mul2(zh, tp);
    u64 h1 = add2(KS1H, q);                      // Fast2Sum: |S1H| >= |q|
    u64 d1 = fma2(h1, K_N1, KS1H);               // S1H - h1
    u64 l1 = add2(add2(d1, q), KS1L);
    u64 uh = mul2(zh, h1);
    u64 uhn = mul2(uh, K_N1);
    u64 ul = fma2(zh, h1, uhn);
    ul = fma2(zh, l1, ul);
    ul = fma2(zl, h1, ul);
    u64 Th = mul2(rh, uh);
    u64 Thn = mul2(Th, K_N1);
    u64 Tl = fma2(rh, uh, Thn);
    Tl = fma2(rh, ul, Tl);
    Tl = fma2(rl, uh, Tl);
    u64 sh = add2(rh, Th);                       // Fast2Sum: |rh| >= |Th|
    u64 st = fma2(sh, K_N1, rh);                 // rh - sh
    st = add2(st, Th);
    st = add2(st, Tl);
    st = add2(st, rl);
    u64 spre = add2(sh, st);

    // ---- cos(r) = 1 + z*(-1/2 + z*(C1ds + z*tail)) ----
    const u64 KC6  = pk2(-1.13596475577881948e-11f, -1.13596475577881948e-11f);
    const u64 KC5  = pk2( 2.08757232129817483e-9f,   2.08757232129817483e-9f);
    const u64 KC4  = pk2(-2.75573143513906633e-7f,  -2.75573143513906633e-7f);
    const u64 KC3  = pk2( 2.48015872894767294e-5f,   2.48015872894767294e-5f);
    const u64 KC2  = pk2(-1.38888892255723476e-3f,  -1.38888892255723476e-3f);
    const u64 KC1H = pk2( 4.16666679084301e-2f,      4.16666679084301e-2f);
    const u64 KC1L = pk2(-1.2417635e-9f,            -1.2417635e-9f);
    const u64 K_NH = pk2(-0.5f, -0.5f);
    const u64 K_1  = pk2(1.0f, 1.0f);

    u64 tc = fma2(zh, KC6, KC5);
    tc = fma2(zh, tc, KC4);
    tc = fma2(zh, tc, KC3);
    tc = fma2(zh, tc, KC2);
    u64 qc = mul2(zh, tc);
    u64 hc = add2(KC1H, qc);                     // Fast2Sum: |C1H| >= |qc|
    u64 dc = fma2(hc, K_N1, KC1H);               // C1H - hc
    u64 lc = add2(add2(dc, qc), KC1L);
    u64 wh = mul2(zh, hc);
    u64 whn = mul2(wh, K_N1);
    u64 wl = fma2(zh, hc, whn);
    wl = fma2(zh, lc, wl);
    wl = fma2(zl, hc, wl);
    u64 gh = add2(K_NH, wh);                     // Fast2Sum: 0.5 >= |wh|
    u64 gt = fma2(gh, K_N1, K_NH);               // -0.5 - gh
    gt = add2(gt, wh);
    u64 gl = add2(gt, wl);
    u64 Uh = mul2(zh, gh);
    u64 Uhn = mul2(Uh, K_N1);
    u64 Ul = fma2(zh, gh, Uhn);
    Ul = fma2(zh, gl, Ul);
    Ul = fma2(zl, gh, Ul);
    u64 ch = add2(K_1, Uh);                      // Fast2Sum: 1 >= |Uh|
    u64 ct = fma2(ch, K_N1, K_1);                // 1 - ch
    ct = add2(ct, Uh);
    ct = add2(ct, Ul);
    u64 cpre = add2(ch, ct);

    float spA, spB, cpA, cpB;
    upk2(spre, spA, spB);
    upk2(cpre, cpA, cpB);

    // quadrant fix per lane (exact, float/int domain)
    float s0 = (ka & 1) ? cpA : spA;
    float c0 = (ka & 1) ? spA : cpA;
    if (ka & 2)       s0 = __int_as_float(__float_as_int(s0) ^ 0x80000000);
    if ((ka + 1) & 2) c0 = __int_as_float(__float_as_int(c0) ^ 0x80000000);
    sA = s0; cA = c0;
    float s1 = (kb & 1) ? cpB : spB;
    float c1 = (kb & 1) ? spB : cpB;
    if (kb & 2)       s1 = __int_as_float(__float_as_int(s1) ^ 0x80000000);
    if ((kb + 1) & 2) c1 = __int_as_float(__float_as_int(c1) ^ 0x80000000);
    sB = s1; cB = c1;
}

// log/exp outputs are NOT amplification-critical -> MUFU (proven R7-R9).
__device__ __forceinline__ float flog(float x) { return __logf(x); }
__device__ __forceinline__ float fexp(float x) { return __expf(x); }

// e1/e2 float-bit-exact to reference (XLA:CPU, no contraction):
// e = fsub(fmul(s, c), fmul(m1, n3)), n3 = -cos (shared product)
__device__ __forceinline__ float log_ratio(float s3, float n3,
                                           float m1, float c1, float c2)
{
    const float pm = 1e-6f;
    const float t  = __fmul_rn(m1, n3);
    float e1 = __fsub_rn(__fmul_rn(s3, c1), t);
    float e2 = __fsub_rn(__fmul_rn(s3, c2), t);
    float la = flog(fmaxf(fabsf(e1), pm));
    float lb = flog(fmaxf(fabsf(e2), pm));
    float v  = __fsub_rn(la, lb);
    return fminf(fmaxf(v, -10.0f), 10.0f);
}

__global__ __launch_bounds__(256)
void sno_kernel(const float* __restrict__ depth,
                const float* __restrict__ ang,
                const float* __restrict__ intr,
                float* __restrict__ out)
{
    int tid = blockIdx.x * blockDim.x + threadIdx.x;   // grid exactly covers NCELL

    int cx = tid % LWD;
    int t  = tid / LWD;
    int cy = t % LHD;
    int b  = t / LHD;

    const float fx = intr[b * 9 + 0];
    const float bx = intr[b * 9 + 2];
    const float fy = intr[b * 9 + 4];
    const float by = intr[b * 9 + 5];

    const int y0 = cy * 4;   // block top row  (== yy0 - 2)
    const int x0 = cx * 4;   // block left col (== xx0 - 2)

    const float* __restrict__ angh = ang + (size_t)(b * 2 + 0) * HD * WD;
    const float* __restrict__ angv = ang + (size_t)(b * 2 + 1) * HD * WD;

    // Hoisted per-row/per-column geometry (bit-exact reuse: b2[c] == -tx[c+1],
    // v2[r] == -ty[r+1]).
    float tx[4], ty[4], a1[4], u1[4];
    #pragma unroll
    for (int i = 0; i < 4; ++i) {
        const float xf = (float)(x0 + i);
        const float yf = (float)(y0 + i);
        tx[i] = __fdiv_rn(__fsub_rn(xf, bx), fx);
        ty[i] = __fdiv_rn(__fsub_rn(yf, by), fy);
        a1[i] = __fadd_rn(__fmul_rn(ty[i], ty[i]), 1.0f);
        u1[i] = __fadd_rn(__fmul_rn(tx[i], tx[i]), 1.0f);
    }

    float lh[4][3];
    float lv[3][4];

    // ---- horizontal: 12 angles, 6 packed sincos ----
    {
        float hv[12];
        #pragma unroll
        for (int r = 0; r < 4; ++r) {
            const float4 hr = *reinterpret_cast<const float4*>(
                angh + (size_t)(y0 + r) * WD + x0);
            hv[3 * r + 0] = hr.x;
            hv[3 * r + 1] = hr.y;
            hv[3 * r + 2] = hr.z;
        }
        #pragma unroll
        for (int i = 0; i < 6; ++i) {
            const int iA = 2 * i, iB = 2 * i + 1;
            const int rA = iA / 3, cA = iA % 3;
            const int rB = iB / 3, cB = iB % 3;
            float sA, coA, sB, coB;
            ffsincos2(hv[iA], hv[iB], sA, coA, sB, coB);
            lh[rA][cA] = log_ratio(sA, -coA, a1[rA], -tx[cA], -tx[cA + 1]);
            lh[rB][cB] = log_ratio(sB, -coB, a1[rB], -tx[cB], -tx[cB + 1]);
        }
    }

    // ---- vertical: 12 angles, 6 packed sincos ----
    #pragma unroll
    for (int r = 0; r < 3; ++r) {
        const float4 vr = *reinterpret_cast<const float4*>(
            angv + (size_t)(y0 + r) * WD + x0);
        float sA, coA, sB, coB;
        ffsincos2(vr.x, vr.y, sA, coA, sB, coB);
        lv[r][0] = log_ratio(sA, -coA, u1[0], -ty[r], -ty[r + 1]);
        lv[r][1] = log_ratio(sB, -coB, u1[1], -ty[r], -ty[r + 1]);
        ffsincos2(vr.z, vr.w, sA, coA, sB, coB);
        lv[r][2] = log_ratio(sA, -coA, u1[2], -ty[r], -ty[r + 1]);
        lv[r][3] = log_ratio(sB, -coB, u1[3], -ty[r], -ty[r + 1]);
    }

    // d[row][col]: row = mm+2, col = nn+2  -> pixel (y0+row, x0+col)
    float d[4][4];
    d[2][2] = flog(depth[tid]);

    #pragma unroll
    for (int m = 0; m < 4; ++m) {
        #pragma unroll
        for (int n = 0; n < 4; ++n) {
            if (m == 0 && n == 0) continue;
            const int mm = (m & 1) ? -((m + 1) >> 1) : (m >> 1);
            const int nn = (n & 1) ? -((n + 1) >> 1) : (n >> 1);

            int lx1 = 0, ly1 = 0, ch1 = 0, dx1 = 0, dy1 = 0;
            int lx2 = 0, ly2 = 0, ch2 = 0, dx2 = 0, dy2 = 0;
            float s1 = 0.0f, s2 = 0.0f;
            const bool has1 = (nn != 0);
            const bool has2 = (mm != 0);
            if (nn < 0)      { lx1 = nn;     ly1 = mm; ch1 = 0; dx1 = nn + 1; dy1 = mm;     s1 = -1.0f; }
            else if (nn > 0) { lx1 = nn - 1; ly1 = mm; ch1 = 0; dx1 = nn - 1; dy1 = mm;     s1 =  1.0f; }
            if (mm > 0)      { lx2 = nn; ly2 = mm - 1; ch2 = 1; dx2 = nn;     dy2 = mm - 1; s2 =  1.0f; }
            else if (mm < 0) { lx2 = nn; ly2 = mm;     ch2 = 1; dx2 = nn;     dy2 = mm + 1; s2 = -1.0f; }
            if (!has1) { lx1 = lx2; ly1 = ly2; ch1 = ch2; dx1 = dx2; dy1 = dy2; s1 = s2; }
            if (!has2) { lx2 = lx1; ly2 = ly1; ch2 = ch1; dx2 = dx1; dy2 = dy1; s2 = s1; }

            const float l1 = (ch1 == 0) ? lh[ly1 + 2][lx1 + 2] : lv[ly1 + 2][lx1 + 2];
            const float l2 = (ch2 == 0) ? lh[ly2 + 2][lx2 + 2] : lv[ly2 + 2][lx2 + 2];

            float acc = __fadd_rn(d[dy1 + 2][dx1 + 2], __fmul_rn(s1, l1));
            acc = __fadd_rn(acc, d[dy2 + 2][dx2 + 2]);
            acc = __fadd_rn(acc, __fmul_rn(s2, l2));
            d[mm + 2][nn + 2] = __fmul_rn(acc, 0.5f);
        }
    }

    #pragma unroll
    for (int r = 0; r < 4; ++r) {
        const int y = y0 + r;
        float4 o;
        o.x = fexp(d[r][0]);
        o.y = fexp(d[r][1]);
        o.z = fexp(d[r][2]);
        o.w = fexp(d[r][3]);
        *reinterpret_cast<float4*>(&out[((size_t)b * HD + y) * WD + x0]) = o;
    }
}

extern "C" void kernel_launch(void* const* d_in, const int* in_sizes, int n_in,
                              void* d_out, int out_size)
{
    const float* depth = (const float*)d_in[0];
    const float* ang   = (const float*)d_in[1];
    const float* intr  = (const float*)d_in[2];
    float* out = (float*)d_out;

    const int threads = 256;
    const int blocks = NCELL / threads;   // exact: 245760 / 256 = 960
    sno_kernel<<<blocks, threads>>>(depth, ang, intr, out);
}

// round 11
// speedup vs baseline: 55.8940x; 1.0677x over previous
#include <cuda_runtime.h>
#include <cuda_bf16.h>

// Problem constants (B, H, W, SCALE) = (8, 384, 1280, 2)
#define BD   8
#define HD   384
#define WD   1280
#define LHD  (HD / 4)    // 96
#define LWD  (WD / 4)    // 320
#define NCELL (BD * LHD * LWD)  // 245760

#define NBLOCKS  592          // 4 blocks/SM x 148 SMs -> exactly one wave
#define NTHREADS 256

typedef unsigned long long u64;

// ---- packed f32x2 primitives (sm_100+): per-lane RN, bit-identical to scalar
__device__ __forceinline__ u64 pk2(float lo, float hi) {
    u64 r; asm("mov.b64 %0, {%1, %2};" : "=l"(r) : "f"(lo), "f"(hi)); return r;
}
__device__ __forceinline__ void upk2(u64 v, float& lo, float& hi) {
    asm("mov.b64 {%0, %1}, %2;" : "=f"(lo), "=f"(hi) : "l"(v));
}
__device__ __forceinline__ u64 fma2(u64 a, u64 b, u64 c) {
    u64 d; asm("fma.rn.f32x2 %0, %1, %2, %3;" : "=l"(d) : "l"(a), "l"(b), "l"(c)); return d;
}
__device__ __forceinline__ u64 mul2(u64 a, u64 b) {
    u64 d; asm("mul.rn.f32x2 %0, %1, %2;" : "=l"(d) : "l"(a), "l"(b)); return d;
}
__device__ __forceinline__ u64 add2(u64 a, u64 b) {
    u64 d; asm("add.rn.f32x2 %0, %1, %2;" : "=l"(d) : "l"(a), "l"(b)); return d;
}

// ---------------------------------------------------------------------------
// Packed two-angle float-float sincos, abs err ~2^-29.5 (error contribution
// proven invisible vs the ~8.9e-5 reference-mismatch floor, R8-R10).
// ---------------------------------------------------------------------------
__device__ __forceinline__ void ffsincos2(float xa, float xb,
                                          float& sA, float& cA,
                                          float& sB, float& cB)
{
    const u64 K_INV  = pk2(0.636619772367581343f, 0.636619772367581343f);
    const u64 K_MAG  = pk2(12582912.0f, 12582912.0f);
    const u64 K_NMAG = pk2(-12582912.0f, -12582912.0f);
    const u64 K_NPH  = pk2(-1.5703125f, -1.5703125f);
    const u64 K_NPM  = pk2(-4.83751297e-4f, -4.83751297e-4f);
    const u64 K_NPL  = pk2(-7.54978995e-8f, -7.54978995e-8f);
    const u64 K_N1   = pk2(-1.0f, -1.0f);

    u64 x = pk2(xa, xb);
    u64 t = fma2(x, K_INV, K_MAG);
    float tlo, thi; upk2(t, tlo, thi);
    int ka = __float_as_int(tlo) - 0x4B400000;   // == (int)fk per lane
    int kb = __float_as_int(thi) - 0x4B400000;
    u64 fk  = add2(t, K_NMAG);                   // exact
    u64 a   = fma2(fk, K_NPH, x);                // exact (Sterbenz)
    u64 p2n = mul2(fk, K_NPM);                   // exact, == -fk*PM
    // TwoSum(a, p2n)
    u64 rh  = add2(a, p2n);
    u64 bb  = fma2(a, K_N1, rh);                 // rh - a
    u64 w1  = fma2(bb, K_N1, rh);                // rh - bb
    u64 w2  = fma2(w1, K_N1, a);                 // a - (rh - bb)
    u64 w3  = fma2(bb, K_N1, p2n);               // p2n - bb
    u64 e1  = add2(w2, w3);
    u64 rl  = fma2(fk, K_NPL, e1);

    u64 zh  = mul2(rh, rh);
    u64 zhn = mul2(zh, K_N1);
    u64 ze  = fma2(rh, rh, zhn);
    u64 zl  = fma2(add2(rh, rh), rl, ze);

    // ---- sin(r) = r + r*z*(S1ds + z*tail) ----
    const u64 KS6  = pk2( 1.58969099521155010e-10f,  1.58969099521155010e-10f);
    const u64 KS5  = pk2(-2.50507602534068634e-8f,  -2.50507602534068634e-8f);
    const u64 KS4  = pk2( 2.75573137070700677e-6f,   2.75573137070700677e-6f);
    const u64 KS3  = pk2(-1.98412698298579493e-4f,  -1.98412698298579493e-4f);
    const u64 KS2  = pk2( 8.33333376795053482e-3f,   8.33333376795053482e-3f);
    const u64 KS1H = pk2(-0.166666671633720398f,    -0.166666671633720398f);
    const u64 KS1L = pk2( 4.9670572e-9f,             4.9670572e-9f);

    u64 tp = fma2(zh, KS6, KS5);
    tp = fma2(zh, tp, KS4);
    tp = fma2(zh, tp, KS3);
    tp = fma2(zh, tp, KS2);
    u64 q  = mul2(zh, tp);
    u64 h1 = add2(KS1H, q);                      // Fast2Sum: |S1H| >= |q|
    u64 d1 = fma2(h1, K_N1, KS1H);               // S1H - h1
    u64 l1 = add2(add2(d1, q), KS1L);
    u64 uh = mul2(zh, h1);
    u64 uhn = mul2(uh, K_N1);
    u64 ul = fma2(zh, h1, uhn);
    ul = fma2(zh, l1, ul);
    ul = fma2(zl, h1, ul);
    u64 Th = mul2(rh, uh);
    u64 Thn = mul2(Th, K_N1);
    u64 Tl = fma2(rh, uh, Thn);
    Tl = fma2(rh, ul, Tl);
    Tl = fma2(rl, uh, Tl);
    u64 sh = add2(rh, Th);                       // Fast2Sum: |rh| >= |Th|
    u64 st = fma2(sh, K_N1, rh);                 // rh - sh
    st = add2(st, Th);
    st = add2(st, Tl);
    st = add2(st, rl);
    u64 spre = add2(sh, st);

    // ---- cos(r) = 1 + z*(-1/2 + z*(C1ds + z*tail)) ----
    const u64 KC6  = pk2(-1.13596475577881948e-11f, -1.13596475577881948e-11f);
    const u64 KC5  = pk2( 2.08757232129817483e-9f,   2.08757232129817483e-9f);
    const u64 KC4  = pk2(-2.75573143513906633e-7f,  -2.75573143513906633e-7f);
    const u64 KC3  = pk2( 2.48015872894767294e-5f,   2.48015872894767294e-5f);
    const u64 KC2  = pk2(-1.38888892255723476e-3f,  -1.38888892255723476e-3f);
    const u64 KC1H = pk2( 4.16666679084301e-2f,      4.16666679084301e-2f);
    const u64 KC1L = pk2(-1.2417635e-9f,            -1.2417635e-9f);
    const u64 K_NH = pk2(-0.5f, -0.5f);
    const u64 K_1  = pk2(1.0f, 1.0f);

    u64 tc = fma2(zh, KC6, KC5);
    tc = fma2(zh, tc, KC4);
    tc = fma2(zh, tc, KC3);
    tc = fma2(zh, tc, KC2);
    u64 qc = mul2(zh, tc);
    u64 hc = add2(KC1H, qc);                     // Fast2Sum: |C1H| >= |qc|
    u64 dc = fma2(hc, K_N1, KC1H);               // C1H - hc
    u64 lc = add2(add2(dc, qc), KC1L);
    u64 wh = mul2(zh, hc);
    u64 whn = mul2(wh, K_N1);
    u64 wl = fma2(zh, hc, whn);
    wl = fma2(zh, lc, wl);
    wl = fma2(zl, hc, wl);
    u64 gh = add2(K_NH, wh);                     // Fast2Sum: 0.5 >= |wh|
    u64 gt = fma2(gh, K_N1, K_NH);               // -0.5 - gh
    gt = add2(gt, wh);
    u64 gl = add2(gt, wl);
    u64 Uh = mul2(zh, gh);
    u64 Uhn = mul2(Uh, K_N1);
    u64 Ul = fma2(zh, gh, Uhn);
    Ul = fma2(zh, gl, Ul);
    Ul = fma2(zl, gh, Ul);
    u64 ch = add2(K_1, Uh);                      // Fast2Sum: 1 >= |Uh|
    u64 ct = fma2(ch, K_N1, K_1);                // 1 - ch
    ct = add2(ct, Uh);
    ct = add2(ct, Ul);
    u64 cpre = add2(ch, ct);

    float spA, spB, cpA, cpB;
    upk2(spre, spA, spB);
    upk2(cpre, cpA, cpB);

    // quadrant fix per lane (exact, float/int domain)
    float s0 = (ka & 1) ? cpA : spA;
    float c0 = (ka & 1) ? spA : cpA;
    if (ka & 2)       s0 = __int_as_float(__float_as_int(s0) ^ 0x80000000);
    if ((ka + 1) & 2) c0 = __int_as_float(__float_as_int(c0) ^ 0x80000000);
    sA = s0; cA = c0;
    float s1 = (kb & 1) ? cpB : spB;
    float c1 = (kb & 1) ? spB : cpB;
    if (kb & 2)       s1 = __int_as_float(__float_as_int(s1) ^ 0x80000000);
    if ((kb + 1) & 2) c1 = __int_as_float(__float_as_int(c1) ^ 0x80000000);
    sB = s1; cB = c1;
}

// log/exp outputs are NOT amplification-critical -> MUFU (proven R7-R10).
__device__ __forceinline__ float flog(float x) { return __logf(x); }
__device__ __forceinline__ float fexp(float x) { return __expf(x); }

// e1/e2 float-bit-exact to reference (XLA:CPU, no contraction):
// e = fsub(fmul(s, c), fmul(m1, n3)), n3 = -cos (shared product)
__device__ __forceinline__ float log_ratio(float s3, float n3,
                                           float m1, float c1, float c2)
{
    const float pm = 1e-6f;
    const float t  = __fmul_rn(m1, n3);
    float e1 = __fsub_rn(__fmul_rn(s3, c1), t);
    float e2 = __fsub_rn(__fmul_rn(s3, c2), t);
    float la = flog(fmaxf(fabsf(e1), pm));
    float lb = flog(fmaxf(fabsf(e2), pm));
    float v  = __fsub_rn(la, lb);
    return fminf(fmaxf(v, -10.0f), 10.0f);
}

__device__ __forceinline__ void process_cell(
    int tid,
    const float* __restrict__ depth,
    const float* __restrict__ ang,
    const float* __restrict__ intr,
    float* __restrict__ out)
{
    int cx = tid % LWD;
    int t  = tid / LWD;
    int cy = t % LHD;
    int b  = t / LHD;

    const float fx = intr[b * 9 + 0];
    const float bx = intr[b * 9 + 2];
    const float fy = intr[b * 9 + 4];
    const float by = intr[b * 9 + 5];

    const int y0 = cy * 4;   // block top row  (== yy0 - 2)
    const int x0 = cx * 4;   // block left col (== xx0 - 2)

    const float* __restrict__ angh = ang + (size_t)(b * 2 + 0) * HD * WD;
    const float* __restrict__ angv = ang + (size_t)(b * 2 + 1) * HD * WD;

    // Hoisted geometry (bit-exact reuse: b2[c] == -tx[c+1], v2[r] == -ty[r+1])
    float tx[4], ty[4], a1[4], u1[4];
    #pragma unroll
    for (int i = 0; i < 4; ++i) {
        const float xf = (float)(x0 + i);
        const float yf = (float)(y0 + i);
        tx[i] = __fdiv_rn(__fsub_rn(xf, bx), fx);
        ty[i] = __fdiv_rn(__fsub_rn(yf, by), fy);
        a1[i] = __fadd_rn(__fmul_rn(ty[i], ty[i]), 1.0f);
        u1[i] = __fadd_rn(__fmul_rn(tx[i], tx[i]), 1.0f);
    }

    float lh[4][3];
    float lv[3][4];

    // ---- horizontal: 12 angles, 6 packed sincos ----
    {
        float hv[12];
        #pragma unroll
        for (int r = 0; r < 4; ++r) {
            const float4 hr = *reinterpret_cast<const float4*>(
                angh + (size_t)(y0 + r) * WD + x0);
            hv[3 * r + 0] = hr.x;
            hv[3 * r + 1] = hr.y;
            hv[3 * r + 2] = hr.z;
        }
        #pragma unroll
        for (int i = 0; i < 6; ++i) {
            const int iA = 2 * i, iB = 2 * i + 1;
            const int rA = iA / 3, cA = iA % 3;
            const int rB = iB / 3, cB = iB % 3;
            float sA, coA, sB, coB;
            ffsincos2(hv[iA], hv[iB], sA, coA, sB, coB);
            lh[rA][cA] = log_ratio(sA, -coA, a1[rA], -tx[cA], -tx[cA + 1]);
            lh[rB][cB] = log_ratio(sB, -coB, a1[rB], -tx[cB], -tx[cB + 1]);
        }
    }

    // ---- vertical: 12 angles, 6 packed sincos ----
    #pragma unroll
    for (int r = 0; r < 3; ++r) {
        const float4 vr = *reinterpret_cast<const float4*>(
            angv + (size_t)(y0 + r) * WD + x0);
        float sA, coA, sB, coB;
        ffsincos2(vr.x, vr.y, sA, coA, sB, coB);
        lv[r][0] = log_ratio(sA, -coA, u1[0], -ty[r], -ty[r + 1]);
        lv[r][1] = log_ratio(sB, -coB, u1[1], -ty[r], -ty[r + 1]);
        ffsincos2(vr.z, vr.w, sA, coA, sB, coB);
        lv[r][2] = log_ratio(sA, -coA, u1[2], -ty[r], -ty[r + 1]);
        lv[r][3] = log_ratio(sB, -coB, u1[3], -ty[r], -ty[r + 1]);
    }

    // d[row][col]: row = mm+2, col = nn+2  -> pixel (y0+row, x0+col)
    float d[4][4];
    d[2][2] = flog(depth[tid]);

    #pragma unroll
    for (int m = 0; m < 4; ++m) {
        #pragma unroll
        for (int n = 0; n < 4; ++n) {
            if (m == 0 && n == 0) continue;
            const int mm = (m & 1) ? -((m + 1) >> 1) : (m >> 1);
            const int nn = (n & 1) ? -((n + 1) >> 1) : (n >> 1);

            int lx1 = 0, ly1 = 0, ch1 = 0, dx1 = 0, dy1 = 0;
            int lx2 = 0, ly2 = 0, ch2 = 0, dx2 = 0, dy2 = 0;
            float s1 = 0.0f, s2 = 0.0f;
            const bool has1 = (nn != 0);
            const bool has2 = (mm != 0);
            if (nn < 0)      { lx1 = nn;     ly1 = mm; ch1 = 0; dx1 = nn + 1; dy1 = mm;     s1 = -1.0f; }
            else if (nn > 0) { lx1 = nn - 1; ly1 = mm; ch1 = 0; dx1 = nn - 1; dy1 = mm;     s1 =  1.0f; }
            if (mm > 0)      { lx2 = nn; ly2 = mm - 1; ch2 = 1; dx2 = nn;     dy2 = mm - 1; s2 =  1.0f; }
            else if (mm < 0) { lx2 = nn; ly2 = mm;     ch2 = 1; dx2 = nn;     dy2 = mm + 1; s2 = -1.0f; }
            if (!has1) { lx1 = lx2; ly1 = ly2; ch1 = ch2; dx1 = dx2; dy1 = dy2; s1 = s2; }
            if (!has2) { lx2 = lx1; ly2 = ly1; ch2 = ch1; dx2 = dx1; dy2 = dy1; s2 = s1; }

            const float l1 = (ch1 == 0) ? lh[ly1 + 2][lx1 + 2] : lv[ly1 + 2][lx1 + 2];
            const float l2 = (ch2 == 0) ? lh[ly2 + 2][lx2 + 2] : lv[ly2 + 2][lx2 + 2];

            float acc = __fadd_rn(d[dy1 + 2][dx1 + 2], __fmul_rn(s1, l1));
            acc = __fadd_rn(acc, d[dy2 + 2][dx2 + 2]);
            acc = __fadd_rn(acc, __fmul_rn(s2, l2));
            d[mm + 2][nn + 2] = __fmul_rn(acc, 0.5f);
        }
    }

    #pragma unroll
    for (int r = 0; r < 4; ++r) {
        const int y = y0 + r;
        float4 o;
        o.x = fexp(d[r][0]);
        o.y = fexp(d[r][1]);
        o.z = fexp(d[r][2]);
        o.w = fexp(d[r][3]);
        *reinterpret_cast<float4*>(&out[((size_t)b * HD + y) * WD + x0]) = o;
    }
}

__global__ __launch_bounds__(NTHREADS, 4)
void sno_kernel(const float* __restrict__ depth,
                const float* __restrict__ ang,
                const float* __restrict__ intr,
                float* __restrict__ out)
{
    // Persistent single-wave mapping: 592 blocks = 4/SM x 148 SMs resident at
    // once; grid-stride loop removes the 1.62-wave quantization tail.
    for (int tid = blockIdx.x * NTHREADS + threadIdx.x;
         tid < NCELL;
         tid += NBLOCKS * NTHREADS) {
        process_cell(tid, depth, ang, intr, out);
    }
}

extern "C" void kernel_launch(void* const* d_in, const int* in_sizes, int n_in,
                              void* d_out, int out_size)
{
    const float* depth = (const float*)d_in[0];
    const float* ang   = (const float*)d_in[1];
    const float* intr  = (const float*)d_in[2];
    float* out = (float*)d_out;

    sno_kernel<<<NBLOCKS, NTHREADS>>>(depth, ang, intr, out);
}

// round 12
// speedup vs baseline: 57.7375x; 1.0330x over previous
#include <cuda_runtime.h>
#include <cuda_bf16.h>

// Problem constants (B, H, W, SCALE) = (8, 384, 1280, 2)
#define BD   8
#define HD   384
#define WD   1280
#define LHD  (HD / 4)    // 96
#define LWD  (WD / 4)    // 320
#define NCELL (BD * LHD * LWD)  // 245760

#define NTHREADS 32
#define NBLOCKS  (NCELL / NTHREADS)   // 7680 single-warp blocks

typedef unsigned long long u64;

// ---- packed f32x2 primitives (sm_100+): per-lane RN, bit-identical to scalar
__device__ __forceinline__ u64 pk2(float lo, float hi) {
    u64 r; asm("mov.b64 %0, {%1, %2};" : "=l"(r) : "f"(lo), "f"(hi)); return r;
}
__device__ __forceinline__ void upk2(u64 v, float& lo, float& hi) {
    asm("mov.b64 {%0, %1}, %2;" : "=f"(lo), "=f"(hi) : "l"(v));
}
__device__ __forceinline__ u64 fma2(u64 a, u64 b, u64 c) {
    u64 d; asm("fma.rn.f32x2 %0, %1, %2, %3;" : "=l"(d) : "l"(a), "l"(b), "l"(c)); return d;
}
__device__ __forceinline__ u64 mul2(u64 a, u64 b) {
    u64 d; asm("mul.rn.f32x2 %0, %1, %2;" : "=l"(d) : "l"(a), "l"(b)); return d;
}
__device__ __forceinline__ u64 add2(u64 a, u64 b) {
    u64 d; asm("add.rn.f32x2 %0, %1, %2;" : "=l"(d) : "l"(a), "l"(b)); return d;
}

// ---------------------------------------------------------------------------
// Packed two-angle float-float sincos, abs err ~2^-29.5 (error contribution
// proven invisible vs the ~8.9e-5 reference-mismatch floor, R8-R11).
// ---------------------------------------------------------------------------
__device__ __forceinline__ void ffsincos2(float xa, float xb,
                                          float& sA, float& cA,
                                          float& sB, float& cB)
{
    const u64 K_INV  = pk2(0.636619772367581343f, 0.636619772367581343f);
    const u64 K_MAG  = pk2(12582912.0f, 12582912.0f);
    const u64 K_NMAG = pk2(-12582912.0f, -12582912.0f);
    const u64 K_NPH  = pk2(-1.5703125f, -1.5703125f);
    const u64 K_NPM  = pk2(-4.83751297e-4f, -4.83751297e-4f);
    const u64 K_NPL  = pk2(-7.54978995e-8f, -7.54978995e-8f);
    const u64 K_N1   = pk2(-1.0f, -1.0f);

    u64 x = pk2(xa, xb);
    u64 t = fma2(x, K_INV, K_MAG);
    float tlo, thi; upk2(t, tlo, thi);
    int ka = __float_as_int(tlo) - 0x4B400000;   // == (int)fk per lane
    int kb = __float_as_int(thi) - 0x4B400000;
    u64 fk  = add2(t, K_NMAG);                   // exact
    u64 a   = fma2(fk, K_NPH, x);                // exact (Sterbenz)
    u64 p2n = mul2(fk, K_NPM);                   // exact, == -fk*PM
    // TwoSum(a, p2n)
    u64 rh  = add2(a, p2n);
    u64 bb  = fma2(a, K_N1, rh);                 // rh - a
    u64 w1  = fma2(bb, K_N1, rh);                // rh - bb
    u64 w2  = fma2(w1, K_N1, a);                 // a - (rh - bb)
    u64 w3  = fma2(bb, K_N1, p2n);               // p2n - bb
    u64 e1  = add2(w2, w3);
    u64 rl  = fma2(fk, K_NPL, e1);

    u64 zh  = mul2(rh, rh);
    u64 zhn = mul2(zh, K_N1);
    u64 ze  = fma2(rh, rh, zhn);
    u64 zl  = fma2(add2(rh, rh), rl, ze);

    // ---- sin(r) = r + r*z*(S1ds + z*tail) ----
    const u64 KS6  = pk2( 1.58969099521155010e-10f,  1.58969099521155010e-10f);
    const u64 KS5  = pk2(-2.50507602534068634e-8f,  -2.50507602534068634e-8f);
    const u64 KS4  = pk2( 2.75573137070700677e-6f,   2.75573137070700677e-6f);
    const u64 KS3  = pk2(-1.98412698298579493e-4f,  -1.98412698298579493e-4f);
    const u64 KS2  = pk2( 8.33333376795053482e-3f,   8.33333376795053482e-3f);
    const u64 KS1H = pk2(-0.166666671633720398f,    -0.166666671633720398f);
    const u64 KS1L = pk2( 4.9670572e-9f,             4.9670572e-9f);

    u64 tp = fma2(zh, KS6, KS5);
    tp = fma2(zh, tp, KS4);
    tp = fma2(zh, tp, KS3);
    tp = fma2(zh, tp, KS2);
    u64 q  = mul2(zh, tp);
    u64 h1 = add2(KS1H, q);                      // Fast2Sum: |S1H| >= |q|
    u64 d1 = fma2(h1, K_N1, KS1H);               // S1H - h1
    u64 l1 = add2(add2(d1, q), KS1L);
    u64 uh = mul2(zh, h1);
    u64 uhn = mul2(uh, K_N1);
    u64 ul = fma2(zh, h1, uhn);
    ul = fma2(zh, l1, ul);
    ul = fma2(zl, h1, ul);
    u64 Th = mul2(rh, uh);
    u64 Thn = mul2(Th, K_N1);
    u64 Tl = fma2(rh, uh, Thn);
    Tl = fma2(rh, ul, Tl);
    Tl = fma2(rl, uh, Tl);
    u64 sh = add2(rh, Th);                       // Fast2Sum: |rh| >= |Th|
    u64 st = fma2(sh, K_N1, rh);                 // rh - sh
    st = add2(st, Th);
    st = add2(st, Tl);
    st = add2(st, rl);
    u64 spre = add2(sh, st);

    // ---- cos(r) = 1 + z*(-1/2 + z*(C1ds + z*tail)) ----
    const u64 KC6  = pk2(-1.13596475577881948e-11f, -1.13596475577881948e-11f);
    const u64 KC5  = pk2( 2.08757232129817483e-9f,   2.08757232129817483e-9f);
    const u64 KC4  = pk2(-2.75573143513906633e-7f,  -2.75573143513906633e-7f);
    const u64 KC3  = pk2( 2.48015872894767294e-5f,   2.48015872894767294e-5f);
    const u64 KC2  = pk2(-1.38888892255723476e-3f,  -1.38888892255723476e-3f);
    const u64 KC1H = pk2( 4.16666679084301e-2f,      4.16666679084301e-2f);
    const u64 KC1L = pk2(-1.2417635e-9f,            -1.2417635e-9f);
    const u64 K_NH = pk2(-0.5f, -0.5f);
    const u64 K_1  = pk2(1.0f, 1.0f);

    u64 tc = fma2(zh, KC6, KC5);
    tc = fma2(zh, tc, KC4);
    tc = fma2(zh, tc, KC3);
    tc = fma2(zh, tc, KC2);
    u64 qc = mul2(zh, tc);
    u64 hc = add2(KC1H, qc);                     // Fast2Sum: |C1H| >= |qc|
    u64 dc = fma2(hc, K_N1, KC1H);               // C1H - hc
    u64 lc = add2(add2(dc, qc), KC1L);
    u64 wh = mul2(zh, hc);
    u64 whn = mul2(wh, K_N1);
    u64 wl = fma2(zh, hc, whn);
    wl = fma2(zh, lc, wl);
    wl = fma2(zl, hc, wl);
    u64 gh = add2(K_NH, wh);                     // Fast2Sum: 0.5 >= |wh|
    u64 gt = fma2(gh, K_N1, K_NH);               // -0.5 - gh
    gt = add2(gt, wh);
    u64 gl = add2(gt, wl);
    u64 Uh = mul2(zh, gh);
    u64 Uhn = mul2(Uh, K_N1);
    u64 Ul = fma2(zh, gh, Uhn);
    Ul = fma2(zh, gl, Ul);
    Ul = fma2(zl, gh, Ul);
    u64 ch = add2(K_1, Uh);                      // Fast2Sum: 1 >= |Uh|
    u64 ct = fma2(ch, K_N1, K_1);                // 1 - ch
    ct = add2(ct, Uh);
    ct = add2(ct, Ul);
    u64 cpre = add2(ch, ct);

    float spA, spB, cpA, cpB;
    upk2(spre, spA, spB);
    upk2(cpre, cpA, cpB);

    // quadrant fix per lane (exact, float/int domain)
    float s0 = (ka & 1) ? cpA : spA;
    float c0 = (ka & 1) ? spA : cpA;
    if (ka & 2)       s0 = __int_as_float(__float_as_int(s0) ^ 0x80000000);
    if ((ka + 1) & 2) c0 = __int_as_float(__float_as_int(c0) ^ 0x80000000);
    sA = s0; cA = c0;
    float s1 = (kb & 1) ? cpB : spB;
    float c1 = (kb & 1) ? spB : cpB;
    if (kb & 2)       s1 = __int_as_float(__float_as_int(s1) ^ 0x80000000);
    if ((kb + 1) & 2) c1 = __int_as_float(__float_as_int(c1) ^ 0x80000000);
    sB = s1; cB = c1;
}

// log/exp outputs are NOT amplification-critical -> MUFU (proven R7-R11).
__device__ __forceinline__ float flog(float x) { return __logf(x); }
__device__ __forceinline__ float fexp(float x) { return __expf(x); }

// e1/e2 float-bit-exact to reference (XLA:CPU, no contraction):
// e = fsub(fmul(s, c), fmul(m1, n3)), n3 = -cos (shared product)
__device__ __forceinline__ float log_ratio(float s3, float n3,
                                           float m1, float c1, float c2)
{
    const float pm = 1e-6f;
    const float t  = __fmul_rn(m1, n3);
    float e1 = __fsub_rn(__fmul_rn(s3, c1), t);
    float e2 = __fsub_rn(__fmul_rn(s3, c2), t);
    float la = flog(fmaxf(fabsf(e1), pm));
    float lb = flog(fmaxf(fabsf(e2), pm));
    float v  = __fsub_rn(la, lb);
    return fminf(fmaxf(v, -10.0f), 10.0f);
}

__global__ __launch_bounds__(NTHREADS, 32)
void sno_kernel(const float* __restrict__ depth,
                const float* __restrict__ ang,
                const float* __restrict__ intr,
                float* __restrict__ out)
{
    // One warp per block, one cell per thread: 7680 single-warp CTAs give the
    // GigaThread work-stealer a 1-warp scheduling quantum -> per-SM load
    // imbalance ~2% instead of the 38% tail of the 592-block persistent grid.
    const int tid = blockIdx.x * NTHREADS + threadIdx.x;

    int cx = tid % LWD;
    int t  = tid / LWD;
    int cy = t % LHD;
    int b  = t / LHD;

    const float fx = intr[b * 9 + 0];
    const float bx = intr[b * 9 + 2];
    const float fy = intr[b * 9 + 4];
    const float by = intr[b * 9 + 5];

    const int y0 = cy * 4;   // block top row  (== yy0 - 2)
    const int x0 = cx * 4;   // block left col (== xx0 - 2)

    const float* __restrict__ angh = ang + (size_t)(b * 2 + 0) * HD * WD;
    const float* __restrict__ angv = ang + (size_t)(b * 2 + 1) * HD * WD;

    // Hoisted geometry (bit-exact reuse: b2[c] == -tx[c+1], v2[r] == -ty[r+1])
    float tx[4], ty[4], a1[4], u1[4];
    #pragma unroll
    for (int i = 0; i < 4; ++i) {
        const float xf = (float)(x0 + i);
        const float yf = (float)(y0 + i);
        tx[i] = __fdiv_rn(__fsub_rn(xf, bx), fx);
        ty[i] = __fdiv_rn(__fsub_rn(yf, by), fy);
        a1[i] = __fadd_rn(__fmul_rn(ty[i], ty[i]), 1.0f);
        u1[i] = __fadd_rn(__fmul_rn(tx[i], tx[i]), 1.0f);
    }

    float lh[4][3];
    float lv[3][4];

    // ---- horizontal: 12 angles, 6 packed sincos ----
    {
        float hv[12];
        #pragma unroll
        for (int r = 0; r < 4; ++r) {
            const float4 hr = *reinterpret_cast<const float4*>(
                angh + (size_t)(y0 + r) * WD + x0);
            hv[3 * r + 0] = hr.x;
            hv[3 * r + 1] = hr.y;
            hv[3 * r + 2] = hr.z;
        }
        #pragma unroll
        for (int i = 0; i < 6; ++i) {
            const int iA = 2 * i, iB = 2 * i + 1;
            const int rA = iA / 3, cA = iA % 3;
            const int rB = iB / 3, cB = iB % 3;
            float sA, coA, sB, coB;
            ffsincos2(hv[iA], hv[iB], sA, coA, sB, coB);
            lh[rA][cA] = log_ratio(sA, -coA, a1[rA], -tx[cA], -tx[cA + 1]);
            lh[rB][cB] = log_ratio(sB, -coB, a1[rB], -tx[cB], -tx[cB + 1]);
        }
    }

    // ---- vertical: 12 angles, 6 packed sincos ----
    #pragma unroll
    for (int r = 0; r < 3; ++r) {
        const float4 vr = *reinterpret_cast<const float4*>(
            angv + (size_t)(y0 + r) * WD + x0);
        float sA, coA, sB, coB;
        ffsincos2(vr.x, vr.y, sA, coA, sB, coB);
        lv[r][0] = log_ratio(sA, -coA, u1[0], -ty[r], -ty[r + 1]);
        lv[r][1] = log_ratio(sB, -coB, u1[1], -ty[r], -ty[r + 1]);
        ffsincos2(vr.z, vr.w, sA, coA, sB, coB);
        lv[r][2] = log_ratio(sA, -coA, u1[2], -ty[r], -ty[r + 1]);
        lv[r][3] = log_ratio(sB, -coB, u1[3], -ty[r], -ty[r + 1]);
    }

    // d[row][col]: row = mm+2, col = nn+2  -> pixel (y0+row, x0+col)
    float d[4][4];
    d[2][2] = flog(depth[tid]);

    #pragma unroll
    for (int m = 0; m < 4; ++m) {
        #pragma unroll
        for (int n = 0; n < 4; ++n) {
            if (m == 0 && n == 0) continue;
            const int mm = (m & 1) ? -((m + 1) >> 1) : (m >> 1);
            const int nn = (n & 1) ? -((n + 1) >> 1) : (n >> 1);

            int lx1 = 0, ly1 = 0, ch1 = 0, dx1 = 0, dy1 = 0;
            int lx2 = 0, ly2 = 0, ch2 = 0, dx2 = 0, dy2 = 0;
            float s1 = 0.0f, s2 = 0.0f;
            const bool has1 = (nn != 0);
            const bool has2 = (mm != 0);
            if (nn < 0)      { lx1 = nn;     ly1 = mm; ch1 = 0; dx1 = nn + 1; dy1 = mm;     s1 = -1.0f; }
            else if (nn > 0) { lx1 = nn - 1; ly1 = mm; ch1 = 0; dx1 = nn - 1; dy1 = mm;     s1 =  1.0f; }
            if (mm > 0)      { lx2 = nn; ly2 = mm - 1; ch2 = 1; dx2 = nn;     dy2 = mm - 1; s2 =  1.0f; }
            else if (mm < 0) { lx2 = nn; ly2 = mm;     ch2 = 1; dx2 = nn;     dy2 = mm + 1; s2 = -1.0f; }
            if (!has1) { lx1 = lx2; ly1 = ly2; ch1 = ch2; dx1 = dx2; dy1 = dy2; s1 = s2; }
            if (!has2) { lx2 = lx1; ly2 = ly1; ch2 = ch1; dx2 = dx1; dy2 = dy1; s2 = s1; }

            const float l1 = (ch1 == 0) ? lh[ly1 + 2][lx1 + 2] : lv[ly1 + 2][lx1 + 2];
            const float l2 = (ch2 == 0) ? lh[ly2 + 2][lx2 + 2] : lv[ly2 + 2][lx2 + 2];

            float acc = __fadd_rn(d[dy1 + 2][dx1 + 2], __fmul_rn(s1, l1));
            acc = __fadd_rn(acc, d[dy2 + 2][dx2 + 2]);
            acc = __fadd_rn(acc, __fmul_rn(s2, l2));
            d[mm + 2][nn + 2] = __fmul_rn(acc, 0.5f);
        }
    }

    #pragma unroll
    for (int r = 0; r < 4; ++r) {
        const int y = y0 + r;
        float4 o;
        o.x = fexp(d[r][0]);
        o.y = fexp(d[r][1]);
        o.z = fexp(d[r][2]);
        o.w = fexp(d[r][3]);
        *reinterpret_cast<float4*>(&out[((size_t)b * HD + y) * WD + x0]) = o;
    }
}

extern "C" void kernel_launch(void* const* d_in, const int* in_sizes, int n_in,
                              void* d_out, int out_size)
{
    const float* depth = (const float*)d_in[0];
    const float* ang   = (const float*)d_in[1];
    const float* intr  = (const float*)d_in[2];
    float* out = (float*)d_out;

    sno_kernel<<<NBLOCKS, NTHREADS>>>(depth, ang, intr, out);
}

// round 13
// speedup vs baseline: 59.9521x; 1.0384x over previous
#include <cuda_runtime.h>
#include <cuda_bf16.h>

// Problem constants (B, H, W, SCALE) = (8, 384, 1280, 2)
#define BD   8
#define HD   384
#define WD   1280
#define LHD  (HD / 4)    // 96
#define LWD  (WD / 4)    // 320
#define NCELL (BD * LHD * LWD)  // 245760

#define NTHREADS 32
#define NBLOCKS  (NCELL / NTHREADS)   // 7680 single-warp blocks

typedef unsigned long long u64;

// ---- packed f32x2 primitives (sm_100+): per-lane RN, bit-identical to scalar
__device__ __forceinline__ u64 pk2(float lo, float hi) {
    u64 r; asm("mov.b64 %0, {%1, %2};" : "=l"(r) : "f"(lo), "f"(hi)); return r;
}
__device__ __forceinline__ void upk2(u64 v, float& lo, float& hi) {
    asm("mov.b64 {%0, %1}, %2;" : "=f"(lo), "=f"(hi) : "l"(v));
}
__device__ __forceinline__ u64 fma2(u64 a, u64 b, u64 c) {
    u64 d; asm("fma.rn.f32x2 %0, %1, %2, %3;" : "=l"(d) : "l"(a), "l"(b), "l"(c)); return d;
}
__device__ __forceinline__ u64 mul2(u64 a, u64 b) {
    u64 d; asm("mul.rn.f32x2 %0, %1, %2;" : "=l"(d) : "l"(a), "l"(b)); return d;
}
__device__ __forceinline__ u64 add2(u64 a, u64 b) {
    u64 d; asm("add.rn.f32x2 %0, %1, %2;" : "=l"(d) : "l"(a), "l"(b)); return d;
}

// ---------------------------------------------------------------------------
// Packed two-angle float-float sincos, abs err ~2^-29.5 (error contribution
// proven invisible vs the ~8.9e-5 reference-mismatch floor, R8-R12).
// ---------------------------------------------------------------------------
__device__ __forceinline__ void ffsincos2(float xa, float xb,
                                          float& sA, float& cA,
                                          float& sB, float& cB)
{
    const u64 K_INV  = pk2(0.636619772367581343f, 0.636619772367581343f);
    const u64 K_MAG  = pk2(12582912.0f, 12582912.0f);
    const u64 K_NMAG = pk2(-12582912.0f, -12582912.0f);
    const u64 K_NPH  = pk2(-1.5703125f, -1.5703125f);
    const u64 K_NPM  = pk2(-4.83751297e-4f, -4.83751297e-4f);
    const u64 K_NPL  = pk2(-7.54978995e-8f, -7.54978995e-8f);
    const u64 K_N1   = pk2(-1.0f, -1.0f);

    u64 x = pk2(xa, xb);
    u64 t = fma2(x, K_INV, K_MAG);
    float tlo, thi; upk2(t, tlo, thi);
    int ka = __float_as_int(tlo) - 0x4B400000;   // == (int)fk per lane
    int kb = __float_as_int(thi) - 0x4B400000;
    u64 fk  = add2(t, K_NMAG);                   // exact
    u64 a   = fma2(fk, K_NPH, x);                // exact (Sterbenz)
    u64 p2n = mul2(fk, K_NPM);                   // exact, == -fk*PM
    // TwoSum(a, p2n)
    u64 rh  = add2(a, p2n);
    u64 bb  = fma2(a, K_N1, rh);                 // rh - a
    u64 w1  = fma2(bb, K_N1, rh);                // rh - bb
    u64 w2  = fma2(w1, K_N1, a);                 // a - (rh - bb)
    u64 w3  = fma2(bb, K_N1, p2n);               // p2n - bb
    u64 e1  = add2(w2, w3);
    u64 rl  = fma2(fk, K_NPL, e1);

    u64 zh  = mul2(rh, rh);
    u64 zhn = mul2(zh, K_N1);
    u64 ze  = fma2(rh, rh, zhn);
    u64 zl  = fma2(add2(rh, rh), rl, ze);

    // ---- sin(r) = r + r*z*(S1ds + z*tail) ----
    const u64 KS6  = pk2( 1.58969099521155010e-10f,  1.58969099521155010e-10f);
    const u64 KS5  = pk2(-2.50507602534068634e-8f,  -2.50507602534068634e-8f);
    const u64 KS4  = pk2( 2.75573137070700677e-6f,   2.75573137070700677e-6f);
    const u64 KS3  = pk2(-1.98412698298579493e-4f,  -1.98412698298579493e-4f);
    const u64 KS2  = pk2( 8.33333376795053482e-3f,   8.33333376795053482e-3f);
    const u64 KS1H = pk2(-0.166666671633720398f,    -0.166666671633720398f);
    const u64 KS1L = pk2( 4.9670572e-9f,             4.9670572e-9f);

    u64 tp = fma2(zh, KS6, KS5);
    tp = fma2(zh, tp, KS4);
    tp = fma2(zh, tp, KS3);
    tp = fma2(zh, tp, KS2);
    u64 q  = mul2(zh, tp);
    u64 h1 = add2(KS1H, q);                      // Fast2Sum: |S1H| >= |q|
    u64 d1 = fma2(h1, K_N1, KS1H);               // S1H - h1
    u64 l1 = add2(add2(d1, q), KS1L);
    u64 uh = mul2(zh, h1);
    u64 uhn = mul2(uh, K_N1);
    u64 ul = fma2(zh, h1, uhn);
    ul = fma2(zh, l1, ul);
    ul = fma2(zl, h1, ul);
    u64 Th = mul2(rh, uh);
    u64 Thn = mul2(Th, K_N1);
    u64 Tl = fma2(rh, uh, Thn);
    Tl = fma2(rh, ul, Tl);
    Tl = fma2(rl, uh, Tl);
    u64 sh = add2(rh, Th);                       // Fast2Sum: |rh| >= |Th|
    u64 st = fma2(sh, K_N1, rh);                 // rh - sh
    st = add2(st, Th);
    st = add2(st, Tl);
    st = add2(st, rl);
    u64 spre = add2(sh, st);

    // ---- cos(r) = 1 + z*(-1/2 + z*(C1ds + z*tail)) ----
    const u64 KC6  = pk2(-1.13596475577881948e-11f, -1.13596475577881948e-11f);
    const u64 KC5  = pk2( 2.08757232129817483e-9f,   2.08757232129817483e-9f);
    const u64 KC4  = pk2(-2.75573143513906633e-7f,  -2.75573143513906633e-7f);
    const u64 KC3  = pk2( 2.48015872894767294e-5f,   2.48015872894767294e-5f);
    const u64 KC2  = pk2(-1.38888892255723476e-3f,  -1.38888892255723476e-3f);
    const u64 KC1H = pk2( 4.16666679084301e-2f,      4.16666679084301e-2f);
    const u64 KC1L = pk2(-1.2417635e-9f,            -1.2417635e-9f);
    const u64 K_NH = pk2(-0.5f, -0.5f);
    const u64 K_1  = pk2(1.0f, 1.0f);

    u64 tc = fma2(zh, KC6, KC5);
    tc = fma2(zh, tc, KC4);
    tc = fma2(zh, tc, KC3);
    tc = fma2(zh, tc, KC2);
    u64 qc = mul2(zh, tc);
    u64 hc = add2(KC1H, qc);                     // Fast2Sum: |C1H| >= |qc|
    u64 dc = fma2(hc, K_N1, KC1H);               // C1H - hc
    u64 lc = add2(add2(dc, qc), KC1L);
    u64 wh = mul2(zh, hc);
    u64 whn = mul2(wh, K_N1);
    u64 wl = fma2(zh, hc, whn);
    wl = fma2(zh, lc, wl);
    wl = fma2(zl, hc, wl);
    u64 gh = add2(K_NH, wh);                     // Fast2Sum: 0.5 >= |wh|
    u64 gt = fma2(gh, K_N1, K_NH);               // -0.5 - gh
    gt = add2(gt, wh);
    u64 gl = add2(gt, wl);
    u64 Uh = mul2(zh, gh);
    u64 Uhn = mul2(Uh, K_N1);
    u64 Ul = fma2(zh, gh, Uhn);
    Ul = fma2(zh, gl, Ul);
    Ul = fma2(zl, gh, Ul);
    u64 ch = add2(K_1, Uh);                      // Fast2Sum: 1 >= |Uh|
    u64 ct = fma2(ch, K_N1, K_1);                // 1 - ch
    ct = add2(ct, Uh);
    ct = add2(ct, Ul);
    u64 cpre = add2(ch, ct);

    float spA, spB, cpA, cpB;
    upk2(spre, spA, spB);
    upk2(cpre, cpA, cpB);

    // quadrant fix per lane (exact, float/int domain)
    float s0 = (ka & 1) ? cpA : spA;
    float c0 = (ka & 1) ? spA : cpA;
    if (ka & 2)       s0 = __int_as_float(__float_as_int(s0) ^ 0x80000000);
    if ((ka + 1) & 2) c0 = __int_as_float(__float_as_int(c0) ^ 0x80000000);
    sA = s0; cA = c0;
    float s1 = (kb & 1) ? cpB : spB;
    float c1 = (kb & 1) ? spB : cpB;
    if (kb & 2)       s1 = __int_as_float(__float_as_int(s1) ^ 0x80000000);
    if ((kb + 1) & 2) c1 = __int_as_float(__float_as_int(c1) ^ 0x80000000);
    sB = s1; cB = c1;
}

// log/exp outputs are NOT amplification-critical -> MUFU (proven R7-R12).
__device__ __forceinline__ float flog(float x) { return __logf(x); }
__device__ __forceinline__ float fexp(float x) { return __expf(x); }

// e1/e2 float-bit-exact to reference (XLA:CPU, no contraction):
// e = fsub(fmul(s, c), fmul(m1, n3)), n3 = -cos (shared product)
__device__ __forceinline__ float log_ratio(float s3, float n3,
                                           float m1, float c1, float c2)
{
    const float pm = 1e-6f;
    const float t  = __fmul_rn(m1, n3);
    float e1 = __fsub_rn(__fmul_rn(s3, c1), t);
    float e2 = __fsub_rn(__fmul_rn(s3, c2), t);
    float la = flog(fmaxf(fabsf(e1), pm));
    float lb = flog(fmaxf(fabsf(e2), pm));
    float v  = __fsub_rn(la, lb);
    return fminf(fmaxf(v, -10.0f), 10.0f);
}

// 128-reg budget (16 single-warp blocks/SM >= the ~12.5 warps actually
// achieved at 64 regs): lets ptxas keep the ~20 packed sincos constants
// resident across all 12 inlined calls instead of rematerializing per call,
// and widens the scheduling window for the independent sin/cos chains.
__global__ __launch_bounds__(NTHREADS, 16)
void sno_kernel(const float* __restrict__ depth,
                const float* __restrict__ ang,
                const float* __restrict__ intr,
                float* __restrict__ out)
{
    const int tid = blockIdx.x * NTHREADS + threadIdx.x;

    int cx = tid % LWD;
    int t  = tid / LWD;
    int cy = t % LHD;
    int b  = t / LHD;

    const float fx = intr[b * 9 + 0];
    const float bx = intr[b * 9 + 2];
    const float fy = intr[b * 9 + 4];
    const float by = intr[b * 9 + 5];

    const int y0 = cy * 4;   // block top row  (== yy0 - 2)
    const int x0 = cx * 4;   // block left col (== xx0 - 2)

    const float* __restrict__ angh = ang + (size_t)(b * 2 + 0) * HD * WD;
    const float* __restrict__ angv = ang + (size_t)(b * 2 + 1) * HD * WD;

    // Hoisted geometry (bit-exact reuse: b2[c] == -tx[c+1], v2[r] == -ty[r+1])
    float tx[4], ty[4], a1[4], u1[4];
    #pragma unroll
    for (int i = 0; i < 4; ++i) {
        const float xf = (float)(x0 + i);
        const float yf = (float)(y0 + i);
        tx[i] = __fdiv_rn(__fsub_rn(xf, bx), fx);
        ty[i] = __fdiv_rn(__fsub_rn(yf, by), fy);
        a1[i] = __fadd_rn(__fmul_rn(ty[i], ty[i]), 1.0f);
        u1[i] = __fadd_rn(__fmul_rn(tx[i], tx[i]), 1.0f);
    }

    float lh[4][3];
    float lv[3][4];

    // ---- horizontal: 12 angles, 6 packed sincos ----
    {
        float hv[12];
        #pragma unroll
        for (int r = 0; r < 4; ++r) {
            const float4 hr = *reinterpret_cast<const float4*>(
                angh + (size_t)(y0 + r) * WD + x0);
            hv[3 * r + 0] = hr.x;
            hv[3 * r + 1] = hr.y;
            hv[3 * r + 2] = hr.z;
        }
        #pragma unroll
        for (int i = 0; i < 6; ++i) {
            const int iA = 2 * i, iB = 2 * i + 1;
            const int rA = iA / 3, cA = iA % 3;
            const int rB = iB / 3, cB = iB % 3;
            float sA, coA, sB, coB;
            ffsincos2(hv[iA], hv[iB], sA, coA, sB, coB);
            lh[rA][cA] = log_ratio(sA, -coA, a1[rA], -tx[cA], -tx[cA + 1]);
            lh[rB][cB] = log_ratio(sB, -coB, a1[rB], -tx[cB], -tx[cB + 1]);
        }
    }

    // ---- vertical: 12 angles, 6 packed sincos ----
    #pragma unroll
    for (int r = 0; r < 3; ++r) {
        const float4 vr = *reinterpret_cast<const float4*>(
            angv + (size_t)(y0 + r) * WD + x0);
        float sA, coA, sB, coB;
        ffsincos2(vr.x, vr.y, sA, coA, sB, coB);
        lv[r][0] = log_ratio(sA, -coA, u1[0], -ty[r], -ty[r + 1]);
        lv[r][1] = log_ratio(sB, -coB, u1[1], -ty[r], -ty[r + 1]);
        ffsincos2(vr.z, vr.w, sA, coA, sB, coB);
        lv[r][2] = log_ratio(sA, -coA, u1[2], -ty[r], -ty[r + 1]);
        lv[r][3] = log_ratio(sB, -coB, u1[3], -ty[r], -ty[r + 1]);
    }

    // d[row][col]: row = mm+2, col = nn+2  -> pixel (y0+row, x0+col)
    float d[4][4];
    d[2][2] = flog(depth[tid]);

    #pragma unroll
    for (int m = 0; m < 4; ++m) {
        #pragma unroll
        for (int n = 0; n < 4; ++n) {
            if (m == 0 && n == 0) continue;
            const int mm = (m & 1) ? -((m + 1) >> 1) : (m >> 1);
            const int nn = (n & 1) ? -((n + 1) >> 1) : (n >> 1);

            int lx1 = 0, ly1 = 0, ch1 = 0, dx1 = 0, dy1 = 0;
            int lx2 = 0, ly2 = 0, ch2 = 0, dx2 = 0, dy2 = 0;
            float s1 = 0.0f, s2 = 0.0f;
            const bool has1 = (nn != 0);
            const bool has2 = (mm != 0);
            if (nn < 0)      { lx1 = nn;     ly1 = mm; ch1 = 0; dx1 = nn + 1; dy1 = mm;     s1 = -1.0f; }
            else if (nn > 0) { lx1 = nn - 1; ly1 = mm; ch1 = 0; dx1 = nn - 1; dy1 = mm;     s1 =  1.0f; }
            if (mm > 0)      { lx2 = nn; ly2 = mm - 1; ch2 = 1; dx2 = nn;     dy2 = mm - 1; s2 =  1.0f; }
            else if (mm < 0) { lx2 = nn; ly2 = mm;     ch2 = 1; dx2 = nn;     dy2 = mm + 1; s2 = -1.0f; }
            if (!has1) { lx1 = lx2; ly1 = ly2; ch1 = ch2; dx1 = dx2; dy1 = dy2; s1 = s2; }
            if (!has2) { lx2 = lx1; ly2 = ly1; ch2 = ch1; dx2 = dx1; dy2 = dy1; s2 = s1; }

            const float l1 = (ch1 == 0) ? lh[ly1 + 2][lx1 + 2] : lv[ly1 + 2][lx1 + 2];
            const float l2 = (ch2 == 0) ? lh[ly2 + 2][lx2 + 2] : lv[ly2 + 2][lx2 + 2];

            float acc = __fadd_rn(d[dy1 + 2][dx1 + 2], __fmul_rn(s1, l1));
            acc = __fadd_rn(acc, d[dy2 + 2][dx2 + 2]);
            acc = __fadd_rn(acc, __fmul_rn(s2, l2));
            d[mm + 2][nn + 2] = __fmul_rn(acc, 0.5f);
        }
    }

    #pragma unroll
    for (int r = 0; r < 4; ++r) {
        const int y = y0 + r;
        float4 o;
        o.x = fexp(d[r][0]);
        o.y = fexp(d[r][1]);
        o.z = fexp(d[r][2]);
        o.w = fexp(d[r][3]);
        *reinterpret_cast<float4*>(&out[((size_t)b * HD + y) * WD + x0]) = o;
    }
}

extern "C" void kernel_launch(void* const* d_in, const int* in_sizes, int n_in,
                              void* d_out, int out_size)
{
    const float* depth = (const float*)d_in[0];
    const float* ang   = (const float*)d_in[1];
    const float* intr  = (const float*)d_in[2];
    float* out = (float*)d_out;

    sno_kernel<<<NBLOCKS, NTHREADS>>>(depth, ang, intr, out);
}

// round 14
// speedup vs baseline: 60.1168x; 1.0027x over previous
#include <cuda_runtime.h>
#include <cuda_bf16.h>

// Problem constants (B, H, W, SCALE) = (8, 384, 1280, 2)
#define BD   8
#define HD   384
#define WD   1280
#define LHD  (HD / 4)    // 96
#define LWD  (WD / 4)    // 320
#define NCELL (BD * LHD * LWD)  // 245760

#define NTHREADS 32
#define NBLOCKS  (NCELL / NTHREADS)   // 7680 single-warp blocks

typedef unsigned long long u64;

// ---- packed f32x2 primitives (sm_100+): per-lane RN, bit-identical to scalar
__device__ __forceinline__ u64 pk2(float lo, float hi) {
    u64 r; asm("mov.b64 %0, {%1, %2};" : "=l"(r) : "f"(lo), "f"(hi)); return r;
}
__device__ __forceinline__ void upk2(u64 v, float& lo, float& hi) {
    asm("mov.b64 {%0, %1}, %2;" : "=f"(lo), "=f"(hi) : "l"(v));
}
__device__ __forceinline__ u64 fma2(u64 a, u64 b, u64 c) {
    u64 d; asm("fma.rn.f32x2 %0, %1, %2, %3;" : "=l"(d) : "l"(a), "l"(b), "l"(c)); return d;
}
__device__ __forceinline__ u64 mul2(u64 a, u64 b) {
    u64 d; asm("mul.rn.f32x2 %0, %1, %2;" : "=l"(d) : "l"(a), "l"(b)); return d;
}
__device__ __forceinline__ u64 add2(u64 a, u64 b) {
    u64 d; asm("add.rn.f32x2 %0, %1, %2;" : "=l"(d) : "l"(a), "l"(b)); return d;
}

// ---------------------------------------------------------------------------
// Packed two-angle float-float sincos returning the QUADRANT CLASS REP:
// (s0, c0) equals the true (sin, cos) up to a GLOBAL sign (exactly), which
// downstream |e| erases bit-exactly. Only the k&1 swap (with one relative
// sign) is applied:  k even -> (s, c) ;  k odd -> (c, -s).
// Polys trimmed to S4/C4 (dropped-term ε ~2.9e-9, calibrated Δrel ~2.6e-4).
// ---------------------------------------------------------------------------
__device__ __forceinline__ void ffsincos2(float xa, float xb,
                                          float& sA, float& cA,
                                          float& sB, float& cB)
{
    const u64 K_INV  = pk2(0.636619772367581343f, 0.636619772367581343f);
    const u64 K_MAG  = pk2(12582912.0f, 12582912.0f);
    const u64 K_NMAG = pk2(-12582912.0f, -12582912.0f);
    const u64 K_NPH  = pk2(-1.5703125f, -1.5703125f);
    const u64 K_NPM  = pk2(-4.83751297e-4f, -4.83751297e-4f);
    const u64 K_NPL  = pk2(-7.54978995e-8f, -7.54978995e-8f);
    const u64 K_N1   = pk2(-1.0f, -1.0f);

    u64 x = pk2(xa, xb);
    u64 t = fma2(x, K_INV, K_MAG);
    float tlo, thi; upk2(t, tlo, thi);
    int pa = __float_as_int(tlo);                // low bits == k (mod 2^22)
    int pb = __float_as_int(thi);
    u64 fk  = add2(t, K_NMAG);                   // exact
    u64 a   = fma2(fk, K_NPH, x);                // exact (Sterbenz)
    u64 p2n = mul2(fk, K_NPM);                   // exact, == -fk*PM
    // TwoSum(a, p2n)
    u64 rh  = add2(a, p2n);
    u64 bb  = fma2(a, K_N1, rh);                 // rh - a
    u64 w1  = fma2(bb, K_N1, rh);                // rh - bb
    u64 w2  = fma2(w1, K_N1, a);                 // a - (rh - bb)
    u64 w3  = fma2(bb, K_N1, p2n);               // p2n - bb
    u64 e1  = add2(w2, w3);
    u64 rl  = fma2(fk, K_NPL, e1);

    u64 zh  = mul2(rh, rh);
    u64 zhn = mul2(zh, K_N1);
    u64 ze  = fma2(rh, rh, zhn);
    u64 zl  = fma2(add2(rh, rh), rl, ze);

    // ---- sin(r) = r + r*z*(S1ds + z*(S2 + z*(S3 + z*S4))) ----
    const u64 KS4  = pk2( 2.75573137070700677e-6f,   2.75573137070700677e-6f);
    const u64 KS3  = pk2(-1.98412698298579493e-4f,  -1.98412698298579493e-4f);
    const u64 KS2  = pk2( 8.33333376795053482e-3f,   8.33333376795053482e-3f);
    const u64 KS1H = pk2(-0.166666671633720398f,    -0.166666671633720398f);
    const u64 KS1L = pk2( 4.9670572e-9f,             4.9670572e-9f);

    u64 tp = fma2(zh, KS4, KS3);
    tp = fma2(zh, tp, KS2);
    u64 q  = mul2(zh, tp);
    u64 h1 = add2(KS1H, q);                      // Fast2Sum: |S1H| >= |q|
    u64 d1 = fma2(h1, K_N1, KS1H);               // S1H - h1
    u64 l1 = add2(add2(d1, q), KS1L);
    u64 uh = mul2(zh, h1);
    u64 uhn = mul2(uh, K_N1);
    u64 ul = fma2(zh, h1, uhn);
    ul = fma2(zh, l1, ul);
    ul = fma2(zl, h1, ul);
    u64 Th = mul2(rh, uh);
    u64 Thn = mul2(Th, K_N1);
    u64 Tl = fma2(rh, uh, Thn);
    Tl = fma2(rh, ul, Tl);
    Tl = fma2(rl, uh, Tl);
    u64 sh = add2(rh, Th);                       // Fast2Sum: |rh| >= |Th|
    u64 st = fma2(sh, K_N1, rh);                 // rh - sh
    st = add2(st, Th);
    st = add2(st, Tl);
    st = add2(st, rl);
    u64 spre = add2(sh, st);

    // ---- cos(r) = 1 + z*(-1/2 + z*(C1ds + z*(C2 + z*(C3 + z*C4)))) ----
    const u64 KC4  = pk2(-2.75573143513906633e-7f,  -2.75573143513906633e-7f);
    const u64 KC3  = pk2( 2.48015872894767294e-5f,   2.48015872894767294e-5f);
    const u64 KC2  = pk2(-1.38888892255723476e-3f,  -1.38888892255723476e-3f);
    const u64 KC1H = pk2( 4.16666679084301e-2f,      4.16666679084301e-2f);
    const u64 KC1L = pk2(-1.2417635e-9f,            -1.2417635e-9f);
    const u64 K_NH = pk2(-0.5f, -0.5f);
    const u64 K_1  = pk2(1.0f, 1.0f);

    u64 tc = fma2(zh, KC4, KC3);
    tc = fma2(zh, tc, KC2);
    u64 qc = mul2(zh, tc);
    u64 hc = add2(KC1H, qc);                     // Fast2Sum: |C1H| >= |qc|
    u64 dc = fma2(hc, K_N1, KC1H);               // C1H - hc
    u64 lc = add2(add2(dc, qc), KC1L);
    u64 wh = mul2(zh, hc);
    u64 whn = mul2(wh, K_N1);
    u64 wl = fma2(zh, hc, whn);
    wl = fma2(zh, lc, wl);
    wl = fma2(zl, hc, wl);
    u64 gh = add2(K_NH, wh);                     // Fast2Sum: 0.5 >= |wh|
    u64 gt = fma2(gh, K_N1, K_NH);               // -0.5 - gh
    gt = add2(gt, wh);
    u64 gl = add2(gt, wl);
    u64 Uh = mul2(zh, gh);
    u64 Uhn = mul2(Uh, K_N1);
    u64 Ul = fma2(zh, gh, Uhn);
    Ul = fma2(zh, gl, Ul);
    Ul = fma2(zl, gh, Ul);
    u64 ch = add2(K_1, Uh);                      // Fast2Sum: 1 >= |Uh|
    u64 ct = fma2(ch, K_N1, K_1);                // 1 - ch
    ct = add2(ct, Uh);
    ct = add2(ct, Ul);
    u64 cpre = add2(ch, ct);

    float spA, spB, cpA, cpB;
    upk2(spre, spA, spB);
    upk2(cpre, cpA, cpB);

    // class-rep quadrant fix: k odd -> (s,c) = (c, -s); k even -> (s, c)
    {
        const bool odd = (pa & 1);
        float s0 = odd ? cpA : spA;
        float cr = odd ? spA : cpA;
        cA = __int_as_float(__float_as_int(cr) ^ (pa << 31));
        sA = s0;
    }
    {
        const bool odd = (pb & 1);
        float s0 = odd ? cpB : spB;
        float cr = odd ? spB : cpB;
        cB = __int_as_float(__float_as_int(cr) ^ (pb << 31));
        sB = s0;
    }
}

__device__ __forceinline__ float fexp(float x) { return __expf(x); }

// Reference: e = fsub(fmul(s, c1), fmul(m1, -cos)) == fadd(fmul(s,c1),
// fmul(m1, cos)) EXACTLY. Takes the class-rep (s3, c0): any global sign
// flip of (s3, c0) flips e exactly; |e| is invariant.
// log difference factored: (lg2a - lg2b)*ln2 -- log outputs not
// amplification-critical (R7-R13 evidence).
__device__ __forceinline__ float log_ratio(float s3, float c0,
                                           float m1, float c1, float c2)
{
    const float pm = 1e-6f;
    const float t  = __fmul_rn(m1, c0);
    float e1 = __fadd_rn(__fmul_rn(s3, c1), t);
    float e2 = __fadd_rn(__fmul_rn(s3, c2), t);
    float la = __log2f(fmaxf(fabsf(e1), pm));
    float lb = __log2f(fmaxf(fabsf(e2), pm));
    float v  = __fmul_rn(__fsub_rn(la, lb), 0.69314718055994530942f);
    return fminf(fmaxf(v, -10.0f), 10.0f);
}

__global__ __launch_bounds__(NTHREADS, 16)
void sno_kernel(const float* __restrict__ depth,
                const float* __restrict__ ang,
                const float* __restrict__ intr,
                float* __restrict__ out)
{
    const int tid = blockIdx.x * NTHREADS + threadIdx.x;

    int cx = tid % LWD;
    int t  = tid / LWD;
    int cy = t % LHD;
    int b  = t / LHD;

    const float fx = intr[b * 9 + 0];
    const float bx = intr[b * 9 + 2];
    const float fy = intr[b * 9 + 4];
    const float by = intr[b * 9 + 5];

    const int y0 = cy * 4;   // block top row  (== yy0 - 2)
    const int x0 = cx * 4;   // block left col (== xx0 - 2)

    const float* __restrict__ angh = ang + (size_t)(b * 2 + 0) * HD * WD;
    const float* __restrict__ angv = ang + (size_t)(b * 2 + 1) * HD * WD;

    // Hoisted geometry (bit-exact reuse: b2[c] == -tx[c+1], v2[r] == -ty[r+1])
    float tx[4], ty[4], a1[4], u1[4];
    #pragma unroll
    for (int i = 0; i < 4; ++i) {
        const float xf = (float)(x0 + i);
        const float yf = (float)(y0 + i);
        tx[i] = __fdiv_rn(__fsub_rn(xf, bx), fx);
        ty[i] = __fdiv_rn(__fsub_rn(yf, by), fy);
        a1[i] = __fadd_rn(__fmul_rn(ty[i], ty[i]), 1.0f);
        u1[i] = __fadd_rn(__fmul_rn(tx[i], tx[i]), 1.0f);
    }

    float lh[4][3];
    float lv[3][4];

    // ---- horizontal: 12 angles, 6 packed sincos ----
    {
        float hv[12];
        #pragma unroll
        for (int r = 0; r < 4; ++r) {
            const float4 hr = *reinterpret_cast<const float4*>(
                angh + (size_t)(y0 + r) * WD + x0);
            hv[3 * r + 0] = hr.x;
            hv[3 * r + 1] = hr.y;
            hv[3 * r + 2] = hr.z;
        }
        #pragma unroll
        for (int i = 0; i < 6; ++i) {
            const int iA = 2 * i, iB = 2 * i + 1;
            const int rA = iA / 3, cA = iA % 3;
            const int rB = iB / 3, cB = iB % 3;
            float sA, coA, sB, coB;
            ffsincos2(hv[iA], hv[iB], sA, coA, sB, coB);
            lh[rA][cA] = log_ratio(sA, coA, a1[rA], -tx[cA], -tx[cA + 1]);
            lh[rB][cB] = log_ratio(sB, coB, a1[rB], -tx[cB], -tx[cB + 1]);
        }
    }

    // ---- vertical: 12 angles, 6 packed sincos ----
    #pragma unroll
    for (int r = 0; r < 3; ++r) {
        const float4 vr = *reinterpret_cast<const float4*>(
            angv + (size_t)(y0 + r) * WD + x0);
        float sA, coA, sB, coB;
        ffsincos2(vr.x, vr.y, sA, coA, sB, coB);
        lv[r][0] = log_ratio(sA, coA, u1[0], -ty[r], -ty[r + 1]);
        lv[r][1] = log_ratio(sB, coB, u1[1], -ty[r], -ty[r + 1]);
        ffsincos2(vr.z, vr.w, sA, coA, sB, coB);
        lv[r][2] = log_ratio(sA, coA, u1[2], -ty[r], -ty[r + 1]);
        lv[r][3] = log_ratio(sB, coB, u1[3], -ty[r], -ty[r + 1]);
    }

    // d[row][col]: row = mm+2, col = nn+2  -> pixel (y0+row, x0+col)
    float d[4][4];
    d[2][2] = __fmul_rn(__log2f(depth[tid]), 0.69314718055994530942f);

    #pragma unroll
    for (int m = 0; m < 4; ++m) {
        #pragma unroll
        for (int n = 0; n < 4; ++n) {
            if (m == 0 && n == 0) continue;
            const int mm = (m & 1) ? -((m + 1) >> 1) : (m >> 1);
            const int nn = (n & 1) ? -((n + 1) >> 1) : (n >> 1);

            int lx1 = 0, ly1 = 0, ch1 = 0, dx1 = 0, dy1 = 0;
            int lx2 = 0, ly2 = 0, ch2 = 0, dx2 = 0, dy2 = 0;
            float s1 = 0.0f, s2 = 0.0f;
            const bool has1 = (nn != 0);
            const bool has2 = (mm != 0);
            if (nn < 0)      { lx1 = nn;     ly1 = mm; ch1 = 0; dx1 = nn + 1; dy1 = mm;     s1 = -1.0f; }
            else if (nn > 0) { lx1 = nn - 1; ly1 = mm; ch1 = 0; dx1 = nn - 1; dy1 = mm;     s1 =  1.0f; }
            if (mm > 0)      { lx2 = nn; ly2 = mm - 1; ch2 = 1; dx2 = nn;     dy2 = mm - 1; s2 =  1.0f; }
            else if (mm < 0) { lx2 = nn; ly2 = mm;     ch2 = 1; dx2 = nn;     dy2 = mm + 1; s2 = -1.0f; }
            if (!has1) { lx1 = lx2; ly1 = ly2; ch1 = ch2; dx1 = dx2; dy1 = dy2; s1 = s2; }
            if (!has2) { lx2 = lx1; ly2 = ly1; ch2 = ch1; dx2 = dx1; dy2 = dy1; s2 = s1; }

            const float l1 = (ch1 == 0) ? lh[ly1 + 2][lx1 + 2] : lv[ly1 + 2][lx1 + 2];
            const float l2 = (ch2 == 0) ? lh[ly2 + 2][lx2 + 2] : lv[ly2 + 2][lx2 + 2];

            float acc = __fadd_rn(d[dy1 + 2][dx1 + 2], __fmul_rn(s1, l1));
            acc = __fadd_rn(acc, d[dy2 + 2][dx2 + 2]);
            acc = __fadd_rn(acc, __fmul_rn(s2, l2));
            d[mm + 2][nn + 2] = __fmul_rn(acc, 0.5f);
        }
    }

    #pragma unroll
    for (int r = 0; r < 4; ++r) {
        const int y = y0 + r;
        float4 o;
        o.x = fexp(d[r][0]);
        o.y = fexp(d[r][1]);
        o.z = fexp(d[r][2]);
        o.w = fexp(d[r][3]);
        *reinterpret_cast<float4*>(&out[((size_t)b * HD + y) * WD + x0]) = o;
    }
}

extern "C" void kernel_launch(void* const* d_in, const int* in_sizes, int n_in,
                              void* d_out, int out_size)
{
    const float* depth = (const float*)d_in[0];
    const float* ang   = (const float*)d_in[1];
    const float* intr  = (const float*)d_in[2];
    float* out = (float*)d_out;

    sno_kernel<<<NBLOCKS, NTHREADS>>>(depth, ang, intr, out);
}

// round 16
// speedup vs baseline: 73.0634x; 1.2154x over previous
#include <cuda_runtime.h>
#include <cuda_bf16.h>

// Problem constants (B, H, W, SCALE) = (8, 384, 1280, 2)
#define BD   8
#define HD   384
#define WD   1280
#define LHD  (HD / 4)    // 96
#define LWD  (WD / 4)    // 320
#define NCELL (BD * LHD * LWD)  // 245760

#define NTHREADS 32
#define NBLOCKS  (NCELL / NTHREADS)   // 7680 single-warp blocks

typedef unsigned long long u64;

// ---- packed f32x2 primitives (sm_100+): per-lane RN, bit-identical to scalar
__device__ __forceinline__ u64 pk2(float lo, float hi) {
    u64 r; asm("mov.b64 %0, {%1, %2};" : "=l"(r) : "f"(lo), "f"(hi)); return r;
}
__device__ __forceinline__ void upk2(u64 v, float& lo, float& hi) {
    asm("mov.b64 {%0, %1}, %2;" : "=f"(lo), "=f"(hi) : "l"(v));
}
__device__ __forceinline__ u64 fma2(u64 a, u64 b, u64 c) {
    u64 d; asm("fma.rn.f32x2 %0, %1, %2, %3;" : "=l"(d) : "l"(a), "l"(b), "l"(c)); return d;
}
__device__ __forceinline__ u64 mul2(u64 a, u64 b) {
    u64 d; asm("mul.rn.f32x2 %0, %1, %2;" : "=l"(d) : "l"(a), "l"(b)); return d;
}
__device__ __forceinline__ u64 add2(u64 a, u64 b) {
    u64 d; asm("add.rn.f32x2 %0, %1, %2;" : "=l"(d) : "l"(a), "l"(b)); return d;
}

// ---------------------------------------------------------------------------
// Lean packed two-angle sincos, CLASS-REP output ((s,c) up to a global sign,
// erased bit-exactly by downstream |e|).
// R15 post-mortem fixes (erratic first-order tails, calibrated ~1.2e-7 -> now
// corrected to ~3e-9):
//   sin(rh+rl) = [rh + T exact] + rl*ch            (ch ~ cos(rh))
//   cos(rh+rl) = [1 - zh/2 exact] + z^2*pc - ze/2 - (rl*rh)*(1 + z*h1)
// where ze = rh^2 - fl(rh^2) exact, u = z*h1 ~ sin(rh)/rh - 1.
// ---------------------------------------------------------------------------
__device__ __forceinline__ void ffsincos2(float xa, float xb,
                                          float& sA, float& cA,
                                          float& sB, float& cB)
{
    const u64 K_INV  = pk2(0.636619772367581343f, 0.636619772367581343f);
    const u64 K_MAG  = pk2(12582912.0f, 12582912.0f);
    const u64 K_NMAG = pk2(-12582912.0f, -12582912.0f);
    const u64 K_NPH  = pk2(-1.5703125f, -1.5703125f);
    const u64 K_NPM  = pk2(-4.83751297e-4f, -4.83751297e-4f);
    const u64 K_NPL  = pk2(-7.54978995e-8f, -7.54978995e-8f);
    const u64 K_N1   = pk2(-1.0f, -1.0f);
    const u64 K_1    = pk2(1.0f, 1.0f);
    const u64 K_HLF  = pk2(0.5f, 0.5f);

    u64 x = pk2(xa, xb);
    u64 t = fma2(x, K_INV, K_MAG);
    float tlo, thi; upk2(t, tlo, thi);
    int pa = __float_as_int(tlo);                // low bits == k
    int pb = __float_as_int(thi);
    u64 fk  = add2(t, K_NMAG);                   // exact
    u64 a   = fma2(fk, K_NPH, x);                // exact (Sterbenz)
    u64 p2n = mul2(fk, K_NPM);                   // exact, == -fk*PM
    // Fast2Sum(a, p2n): r = rh + e1 (+ fk*PL tail); |a|<|p2n| only for tiny r
    u64 rh = add2(a, p2n);
    u64 zb = fma2(a, K_N1, rh);                  // rh - a
    u64 e1 = fma2(zb, K_N1, p2n);                // p2n - zb
    u64 rl = fma2(fk, K_NPL, e1);                // |rl| <= ~3.2e-7

    u64 zh  = mul2(rh, rh);
    u64 zhn = mul2(zh, K_N1);
    u64 ze  = fma2(rh, rh, zhn);                 // rh^2 - zh, exact residual

    // exact split of (1 - zh/2)
    u64 hm = mul2(zh, K_HLF);                    // zh/2, exact
    u64 ch = fma2(hm, K_N1, K_1);                // fl(1 - zh/2)
    u64 t1 = fma2(ch, K_N1, K_1);                // 1 - ch (exact, Sterbenz)
    u64 cl = fma2(hm, K_N1, t1);                 // exact lo part

    // ---- sin ----
    const u64 KS4  = pk2( 2.75573137070700677e-6f,   2.75573137070700677e-6f);
    const u64 KS3  = pk2(-1.98412698298579493e-4f,  -1.98412698298579493e-4f);
    const u64 KS2  = pk2( 8.33333376795053482e-3f,   8.33333376795053482e-3f);
    const u64 KS1  = pk2(-0.166666671633720398f,    -0.166666671633720398f);

    u64 h1 = fma2(zh, KS4, KS3);
    h1 = fma2(zh, h1, KS2);
    h1 = fma2(zh, h1, KS1);
    u64 u  = mul2(zh, h1);                       // ~ sin(rh)/rh - 1
    u64 T  = mul2(rh, u);
    u64 sh = add2(rh, T);                        // Fast2Sum: |rh| >= |T|
    u64 sb = fma2(rh, K_N1, sh);                 // sh - rh
    u64 se = fma2(sb, K_N1, T);                  // exact tail of rh+T
    u64 rlc = mul2(rl, ch);                      // rl*cos(rh) to ~1e-14
    u64 stl = add2(se, rlc);
    u64 spre = add2(sh, stl);

    // ---- cos ----
    const u64 KC4  = pk2(-2.75573143513906633e-7f,  -2.75573143513906633e-7f);
    const u64 KC3  = pk2( 2.48015872894767294e-5f,   2.48015872894767294e-5f);
    const u64 KC2  = pk2(-1.38888892255723476e-3f,  -1.38888892255723476e-3f);
    const u64 KC1  = pk2( 4.16666679084301e-2f,      4.16666679084301e-2f);

    u64 pc = fma2(zh, KC4, KC3);
    pc = fma2(zh, pc, KC2);
    pc = fma2(zh, pc, KC1);
    u64 z2 = mul2(zh, zh);
    u64 co = fma2(z2, pc, cl);
    u64 zeh = mul2(ze, K_HLF);
    co = fma2(zeh, K_N1, co);                    // - ze/2
    u64 sfac = add2(K_1, u);                     // ~ sin(rh)/rh
    u64 rr  = mul2(rl, rh);
    u64 rrc = mul2(rr, sfac);
    co = fma2(rrc, K_N1, co);                    // - rl*sin(rh)
    u64 cpre = add2(ch, co);

    float spA, spB, cpA, cpB;
    upk2(spre, spA, spB);
    upk2(cpre, cpA, cpB);

    // class-rep quadrant fix: k odd -> (s,c) = (c, -s); k even -> (s, c)
    {
        const bool odd = (pa & 1);
        float s0 = odd ? cpA : spA;
        float cr = odd ? spA : cpA;
        cA = __int_as_float(__float_as_int(cr) ^ (pa << 31));
        sA = s0;
    }
    {
        const bool odd = (pb & 1);
        float s0 = odd ? cpB : spB;
        float cr = odd ? spB : cpB;
        cB = __int_as_float(__float_as_int(cr) ^ (pb << 31));
        sB = s0;
    }
}

__device__ __forceinline__ float fexp(float x) { return __expf(x); }

// e = fadd(fmul(s, c1), fmul(m1, c0)) -- |e| invariant under the class-rep
// global sign. log difference via log2*ln2 (outputs non-amplification-
// critical, R7-R14 evidence).
__device__ __forceinline__ float log_ratio(float s3, float c0,
                                           float m1, float c1, float c2)
{
    const float pm = 1e-6f;
    const float t  = __fmul_rn(m1, c0);
    float e1 = __fadd_rn(__fmul_rn(s3, c1), t);
    float e2 = __fadd_rn(__fmul_rn(s3, c2), t);
    float la = __log2f(fmaxf(fabsf(e1), pm));
    float lb = __log2f(fmaxf(fabsf(e2), pm));
    float v  = __fmul_rn(__fsub_rn(la, lb), 0.69314718055994530942f);
    return fminf(fmaxf(v, -10.0f), 10.0f);
}

__global__ __launch_bounds__(NTHREADS, 16)
void sno_kernel(const float* __restrict__ depth,
                const float* __restrict__ ang,
                const float* __restrict__ intr,
                float* __restrict__ out)
{
    const int tid = blockIdx.x * NTHREADS + threadIdx.x;

    int cx = tid % LWD;
    int t  = tid / LWD;
    int cy = t % LHD;
    int b  = t / LHD;

    const float fx = intr[b * 9 + 0];
    const float bx = intr[b * 9 + 2];
    const float fy = intr[b * 9 + 4];
    const float by = intr[b * 9 + 5];

    const int y0 = cy * 4;   // block top row  (== yy0 - 2)
    const int x0 = cx * 4;   // block left col (== xx0 - 2)

    const float* __restrict__ angh = ang + (size_t)(b * 2 + 0) * HD * WD;
    const float* __restrict__ angv = ang + (size_t)(b * 2 + 1) * HD * WD;

    // Hoisted geometry (bit-exact reuse: b2[c] == -tx[c+1], v2[r] == -ty[r+1])
    float tx[4], ty[4], a1[4], u1[4];
    #pragma unroll
    for (int i = 0; i < 4; ++i) {
        const float xf = (float)(x0 + i);
        const float yf = (float)(y0 + i);
        tx[i] = __fdiv_rn(__fsub_rn(xf, bx), fx);
        ty[i] = __fdiv_rn(__fsub_rn(yf, by), fy);
        a1[i] = __fadd_rn(__fmul_rn(ty[i], ty[i]), 1.0f);
        u1[i] = __fadd_rn(__fmul_rn(tx[i], tx[i]), 1.0f);
    }

    float lh[4][3];
    float lv[3][4];

    // ---- horizontal: 12 angles, 6 packed sincos ----
    {
        float hv[12];
        #pragma unroll
        for (int r = 0; r < 4; ++r) {
            const float4 hr = *reinterpret_cast<const float4*>(
                angh + (size_t)(y0 + r) * WD + x0);
            hv[3 * r + 0] = hr.x;
            hv[3 * r + 1] = hr.y;
            hv[3 * r + 2] = hr.z;
        }
        #pragma unroll
        for (int i = 0; i < 6; ++i) {
            const int iA = 2 * i, iB = 2 * i + 1;
            const int rA = iA / 3, cA = iA % 3;
            const int rB = iB / 3, cB = iB % 3;
            float sA, coA, sB, coB;
            ffsincos2(hv[iA], hv[iB], sA, coA, sB, coB);
            lh[rA][cA] = log_ratio(sA, coA, a1[rA], -tx[cA], -tx[cA + 1]);
            lh[rB][cB] = log_ratio(sB, coB, a1[rB], -tx[cB], -tx[cB + 1]);
        }
    }

    // ---- vertical: 12 angles, 6 packed sincos ----
    #pragma unroll
    for (int r = 0; r < 3; ++r) {
        const float4 vr = *reinterpret_cast<const float4*>(
            angv + (size_t)(y0 + r) * WD + x0);
        float sA, coA, sB, coB;
        ffsincos2(vr.x, vr.y, sA, coA, sB, coB);
        lv[r][0] = log_ratio(sA, coA, u1[0], -ty[r], -ty[r + 1]);
        lv[r][1] = log_ratio(sB, coB, u1[1], -ty[r], -ty[r + 1]);
        ffsincos2(vr.z, vr.w, sA, coA, sB, coB);
        lv[r][2] = log_ratio(sA, coA, u1[2], -ty[r], -ty[r + 1]);
        lv[r][3] = log_ratio(sB, coB, u1[3], -ty[r], -ty[r + 1]);
    }

    // d[row][col]: row = mm+2, col = nn+2  -> pixel (y0+row, x0+col)
    float d[4][4];
    d[2][2] = __fmul_rn(__log2f(depth[tid]), 0.69314718055994530942f);

    #pragma unroll
    for (int m = 0; m < 4; ++m) {
        #pragma unroll
        for (int n = 0; n < 4; ++n) {
            if (m == 0 && n == 0) continue;
            const int mm = (m & 1) ? -((m + 1) >> 1) : (m >> 1);
            const int nn = (n & 1) ? -((n + 1) >> 1) : (n >> 1);

            int lx1 = 0, ly1 = 0, ch1 = 0, dx1 = 0, dy1 = 0;
            int lx2 = 0, ly2 = 0, ch2 = 0, dx2 = 0, dy2 = 0;
            float s1 = 0.0f, s2 = 0.0f;
            const bool has1 = (nn != 0);
            const bool has2 = (mm != 0);
            if (nn < 0)      { lx1 = nn;     ly1 = mm; ch1 = 0; dx1 = nn + 1; dy1 = mm;     s1 = -1.0f; }
            else if (nn > 0) { lx1 = nn - 1; ly1 = mm; ch1 = 0; dx1 = nn - 1; dy1 = mm;     s1 =  1.0f; }
            if (mm > 0)      { lx2 = nn; ly2 = mm - 1; ch2 = 1; dx2 = nn;     dy2 = mm - 1; s2 =  1.0f; }
            else if (mm < 0) { lx2 = nn; ly2 = mm;     ch2 = 1; dx2 = nn;     dy2 = mm + 1; s2 = -1.0f; }
            if (!has1) { lx1 = lx2; ly1 = ly2; ch1 = ch2; dx1 = dx2; dy1 = dy2; s1 = s2; }
            if (!has2) { lx2 = lx1; ly2 = ly1; ch2 = ch1; dx2 = dx1; dy2 = dy1; s2 = s1; }

            const float l1 = (ch1 == 0) ? lh[ly1 + 2][lx1 + 2] : lv[ly1 + 2][lx1 + 2];
            const float l2 = (ch2 == 0) ? lh[ly2 + 2][lx2 + 2] : lv[ly2 + 2][lx2 + 2];

            float acc = __fadd_rn(d[dy1 + 2][dx1 + 2], __fmul_rn(s1, l1));
            acc = __fadd_rn(acc, d[dy2 + 2][dx2 + 2]);
            acc = __fadd_rn(acc, __fmul_rn(s2, l2));
            d[mm + 2][nn + 2] = __fmul_rn(acc, 0.5f);
        }
    }

    #pragma unroll
    for (int r = 0; r < 4; ++r) {
        const int y = y0 + r;
        float4 o;
        o.x = fexp(d[r][0]);
        o.y = fexp(d[r][1]);
        o.z = fexp(d[r][2]);
        o.w = fexp(d[r][3]);
        *reinterpret_cast<float4*>(&out[((size_t)b * HD + y) * WD + x0]) = o;
    }
}

extern "C" void kernel_launch(void* const* d_in, const int* in_sizes, int n_in,
                              void* d_out, int out_size)
{
    const float* depth = (const float*)d_in[0];
    const float* ang   = (const float*)d_in[1];
    const float* intr  = (const float*)d_in[2];
    float* out = (float*)d_out;

    sno_kernel<<<NBLOCKS, NTHREADS>>>(depth, ang, intr, out);
}